// round 11
// baseline (speedup 1.0000x reference)
#include <cuda_runtime.h>
#include <cuda_fp16.h>
#include <math.h>
#include <stdint.h>

#define BB   4
#define TT   1024
#define CC   1024
#define HH   16
#define DD   64
#define BT   (BB*TT)          // 4096

// Scratch (allocation-free rule: __device__ globals)
__device__ __half g_Qh[BT * CC];
__device__ __half g_Kh[BT * CC];
__device__ __half g_Vh[BT * CC];
__device__ __half g_Yh[BT * CC];
__device__ __half g_Xh[BT * CC];          // fp16-rounded x
__device__ __half g_Wh[4 * CC * CC];      // fp16-rounded Wq|Wk|Wv|Wp

// ---------------------------------------------------------------------------
// helpers
// ---------------------------------------------------------------------------
__device__ __forceinline__ uint2 f4_to_h4(float4 v) {
    __half2 a = __floats2half2_rn(v.x, v.y);
    __half2 b = __floats2half2_rn(v.z, v.w);
    uint2 r;
    r.x = *(uint32_t*)&a;
    r.y = *(uint32_t*)&b;
    return r;
}

__device__ __forceinline__ void mma_f16(float* c, const uint32_t* a, const uint32_t* b) {
    asm volatile(
        "mma.sync.aligned.m16n8k16.row.col.f32.f16.f16.f32 "
        "{%0,%1,%2,%3}, {%4,%5,%6,%7}, {%8,%9}, {%0,%1,%2,%3};"
        : "+f"(c[0]), "+f"(c[1]), "+f"(c[2]), "+f"(c[3])
        : "r"(a[0]), "r"(a[1]), "r"(a[2]), "r"(a[3]), "r"(b[0]), "r"(b[1]));
}

__device__ __forceinline__ void ldsm_x4(uint32_t& r0, uint32_t& r1,
                                        uint32_t& r2, uint32_t& r3, uint32_t addr) {
    asm volatile("ldmatrix.sync.aligned.m8n8.x4.shared.b16 {%0,%1,%2,%3}, [%4];"
                 : "=r"(r0), "=r"(r1), "=r"(r2), "=r"(r3) : "r"(addr));
}
__device__ __forceinline__ void ldsm_x4t(uint32_t& r0, uint32_t& r1,
                                         uint32_t& r2, uint32_t& r3, uint32_t addr) {
    asm volatile("ldmatrix.sync.aligned.m8n8.x4.trans.shared.b16 {%0,%1,%2,%3}, [%4];"
                 : "=r"(r0), "=r"(r1), "=r"(r2), "=r"(r3) : "r"(addr));
}

#define CPA16(dst_u32, src_ptr) \
    asm volatile("cp.async.cg.shared.global [%0], [%1], 16;" \
                 :: "r"(dst_u32), "l"(src_ptr))
#define CPCOMMIT() asm volatile("cp.async.commit_group;")
#define CPWAIT(n)  asm volatile("cp.async.wait_group %0;" :: "n"(n))

// ---------------------------------------------------------------------------
// prepass: fp16-round x -> g_Xh, weights -> g_Wh (concat)
// ---------------------------------------------------------------------------
__global__ void prepass(const float* __restrict__ x,
                        const float* __restrict__ wq, const float* __restrict__ wk,
                        const float* __restrict__ wv, const float* __restrict__ wp)
{
    int which = blockIdx.y;
    const float* src;
    __half* dst;
    int n4;
    if (which == 0) { src = x;  dst = g_Xh; n4 = BT * CC / 4; }
    else {
        src = (which == 1) ? wq : (which == 2) ? wk : (which == 3) ? wv : wp;
        dst = g_Wh + (size_t)(which - 1) * CC * CC;
        n4 = CC * CC / 4;
    }
    for (int i = blockIdx.x * blockDim.x + threadIdx.x; i < n4;
         i += gridDim.x * blockDim.x) {
        float4 v = ((const float4*)src)[i];
        ((uint2*)dst)[i] = f4_to_h4(v);
    }
}

// ---------------------------------------------------------------------------
// C[M,N] = A[M,K] @ W[N,K]^T, FP16 MMA m16n8k16, inputs pre-rounded fp16.
// 128x128 tile, BK=32, 512 threads, 4-stage cp.async, ldmatrix fragments.
// (R7 configuration — known good.)
// ---------------------------------------------------------------------------
#define AST 40                   // halfs per row (80 bytes)
#define GSTG (128 * AST * 2)     // stage bytes per array: 10240
#define NTG 32                   // K/32
__global__ __launch_bounds__(512, 1)
void gemm_f16_nt(const __half* __restrict__ A, const __half* __restrict__ Wb,
                 __half* __restrict__ H0, __half* __restrict__ H1,
                 __half* __restrict__ H2, float* __restrict__ C0, int ro)
{
    const __half* Bw = Wb + (size_t)blockIdx.z * CC * CC;
    __half* H = (blockIdx.z == 0) ? H0 : (blockIdx.z == 1 ? H1 : H2);

    extern __shared__ char smraw[];
    uint32_t sAu = (uint32_t)__cvta_generic_to_shared(smraw);
    uint32_t sBu = sAu + 4 * GSTG;

    const int tid  = threadIdx.x;
    const int lane = tid & 31;
    const int warp = tid >> 5;
    const int wm   = (warp & 3) * 32;
    const int wn   = (warp >> 2) * 32;

    const int lrow = lane & 15;
    const int lkof = (lane & 16) ? 8 : 0;     // halfs
    const uint32_t aoff0 = ((wm + lrow)      * AST + lkof) * 2;
    const uint32_t aoff1 = ((wm + 16 + lrow) * AST + lkof) * 2;
    const uint32_t boff0 = ((wn + lrow)      * AST + lkof) * 2;
    const uint32_t boff1 = ((wn + 16 + lrow) * AST + lkof) * 2;

    const __half* Abase = A  + (size_t)(blockIdx.y * 128) * CC;
    const __half* Bbase = Bw + (size_t)(blockIdx.x * 128) * CC;

    auto load_stage = [&](int kt, int s) {
        int row = tid >> 2, seg = tid & 3;               // 512 granules per array
        CPA16(sAu + s * GSTG + row * 80 + seg * 16,
              Abase + (size_t)row * CC + kt * 32 + seg * 8);
        CPA16(sBu + s * GSTG + row * 80 + seg * 16,
              Bbase + (size_t)row * CC + kt * 32 + seg * 8);
        CPCOMMIT();
    };

    load_stage(0, 0);
    load_stage(1, 1);
    load_stage(2, 2);

    float acc[2][4][4];
    #pragma unroll
    for (int i = 0; i < 2; i++)
        #pragma unroll
        for (int j = 0; j < 4; j++)
            #pragma unroll
            for (int k = 0; k < 4; k++) acc[i][j][k] = 0.f;

    for (int kt = 0; kt < NTG; kt++) {
        if (kt <= NTG - 3)      { CPWAIT(2); }
        else if (kt == NTG - 2) { CPWAIT(1); }
        else                    { CPWAIT(0); }
        __syncthreads();

        if (kt + 3 < NTG) load_stage(kt + 3, (kt + 3) & 3);

        const uint32_t AbU = sAu + (kt & 3) * GSTG;
        const uint32_t BbU = sBu + (kt & 3) * GSTG;

        #pragma unroll
        for (int ks = 0; ks < 2; ks++) {                 // 2 x k16
            uint32_t af[2][4], bf[4][2];
            ldsm_x4(af[0][0], af[0][1], af[0][2], af[0][3], AbU + aoff0 + ks * 32);
            ldsm_x4(af[1][0], af[1][1], af[1][2], af[1][3], AbU + aoff1 + ks * 32);
            ldsm_x4(bf[0][0], bf[1][0], bf[0][1], bf[1][1], BbU + boff0 + ks * 32);
            ldsm_x4(bf[2][0], bf[3][0], bf[2][1], bf[3][1], BbU + boff1 + ks * 32);
            #pragma unroll
            for (int mt = 0; mt < 2; mt++)
                #pragma unroll
                for (int nt = 0; nt < 4; nt++)
                    mma_f16(acc[mt][nt], af[mt], bf[nt]);
        }
    }

    #pragma unroll
    for (int mt = 0; mt < 2; mt++) {
        int r0 = blockIdx.y * 128 + wm + mt * 16 + (lane >> 2);
        #pragma unroll
        for (int nt = 0; nt < 4; nt++) {
            int c0 = blockIdx.x * 128 + wn + nt * 8 + (lane & 3) * 2;
            if (ro) {
                __half2 h01 = __floats2half2_rn(acc[mt][nt][0], acc[mt][nt][1]);
                __half2 h23 = __floats2half2_rn(acc[mt][nt][2], acc[mt][nt][3]);
                *(__half2*)&H[(size_t)r0 * CC + c0]       = h01;
                *(__half2*)&H[(size_t)(r0 + 8) * CC + c0] = h23;
            } else {
                *(float2*)&C0[(size_t)r0 * CC + c0] =
                    make_float2(acc[mt][nt][0], acc[mt][nt][1]);
                *(float2*)&C0[(size_t)(r0 + 8) * CC + c0] =
                    make_float2(acc[mt][nt][2], acc[mt][nt][3]);
            }
        }
    }
}

// ---------------------------------------------------------------------------
// Fused attention: scores + ALiBi + softmax + attn write + PV + Y write.
// block=(b,h,16q), 256 thr, 2 CTAs/SM. After softmax, P (fp16) overwrites the
// fp32 score strip in-place (two-pass scheme keeps reads ahead of clobbers);
// V reuses the K double buffer; V chunk 0/1 loads overlap softmax.
// ---------------------------------------------------------------------------
#define QT   16
#define SSST 1028
#define PHST 1048                // P fp16 row stride in halfs (2096B: 8 distinct phases)
#define QST 72
#define KST 72
#define KBUFB (128 * KST * 2)    // stage bytes: 18432
__global__ __launch_bounds__(256, 2)
void attn_fused_kernel(const __half* __restrict__ Q, const __half* __restrict__ Km,
                       const __half* __restrict__ V,
                       float* __restrict__ attn, __half* __restrict__ Y)
{
    extern __shared__ char smraw[];
    float*  sS = (float*)smraw;                        // QT*1028 floats (reused as P fp16)
    __half* sQ = (__half*)(smraw + QT * SSST * 4);     // QT*72 halfs
    char*   sK = smraw + QT * SSST * 4 + QT * QST * 2; // 2 * KBUFB (K then V chunks)
    uint32_t sSu = (uint32_t)__cvta_generic_to_shared(sS);
    uint32_t sQu = (uint32_t)__cvta_generic_to_shared(sQ);
    uint32_t sKu = (uint32_t)__cvta_generic_to_shared(sK);

    const int tid  = threadIdx.x;
    const int lane = tid & 31;
    const int warp = tid >> 5;           // 0..7
    const int qb   = blockIdx.x * QT;
    const int h    = blockIdx.y;
    const int b    = blockIdx.z;

    const float scale = 0.125f;
    const float slope = exp2f(-0.5f * (float)(h + 1));

    const int wn = warp;                 // 16-col chunk per warp (QK phase)

    const int lrow = lane & 15;
    const int lkof = (lane & 16) ? 8 : 0;
    const uint32_t koff = ((wn * 16 + lrow) * KST + lkof) * 2;

    const __half* Kb = Km + ((size_t)(b * TT)) * CC + h * DD;
    const __half* Vb = V  + ((size_t)(b * TT)) * CC + h * DD;

    // 128-row chunk loader (K or V; same layout, stride KST)
    auto issueKV = [&](const __half* base0, int c, int buf) {
        const __half* base = base0 + (size_t)(c * 128) * CC;
        #pragma unroll
        for (int i = 0; i < 4; i++) {
            int g = tid + i * 256;              // 1024 granules
            int row = g >> 3, seg = g & 7;
            CPA16(sKu + buf * KBUFB + row * (KST * 2) + seg * 16,
                  base + (size_t)row * CC + seg * 8);
        }
        CPCOMMIT();
    };

    issueKV(Kb, 0, 0);

    // Q tile [16 x 64] halfs -> sQ
    if (tid < 128) {
        const __half* Qb = Q + ((size_t)(b * TT + qb)) * CC + h * DD;
        int r = tid >> 3, seg = tid & 7;
        *(uint4*)(sQ + r * QST + seg * 8) =
            *(const uint4*)(Qb + (size_t)r * CC + seg * 8);
    }
    __syncthreads();

    // preload Q fragments (loop-invariant; m16 = all QT rows)
    uint32_t aq[4][4];
    {
        uint32_t qoff = sQu + (lrow * QST + lkof) * 2;
        #pragma unroll
        for (int ks = 0; ks < 4; ks++)
            ldsm_x4(aq[ks][0], aq[ks][1], aq[ks][2], aq[ks][3], qoff + ks * 32);
    }

    // ---- QK phase: 8 chunks of 128 K-rows, double buffered ----
    int buf = 0;
    for (int c = 0; c < 8; c++) {
        if (c + 1 < 8) issueKV(Kb, c + 1, buf ^ 1);
        if (c < 7) { CPWAIT(1); } else { CPWAIT(0); }
        __syncthreads();

        const uint32_t KU = sKu + buf * KBUFB;
        float cr[2][4];
        #pragma unroll
        for (int nt = 0; nt < 2; nt++)
            #pragma unroll
            for (int i = 0; i < 4; i++) cr[nt][i] = 0.f;

        #pragma unroll
        for (int ks = 0; ks < 4; ks++) {
            uint32_t bf2[2][2];
            ldsm_x4(bf2[0][0], bf2[1][0], bf2[0][1], bf2[1][1], KU + koff + ks * 32);
            mma_f16(cr[0], aq[ks], bf2[0]);
            mma_f16(cr[1], aq[ks], bf2[1]);
        }

        const int kc = c * 128;
        #pragma unroll
        for (int nt = 0; nt < 2; nt++) {
            int r0 = lane >> 2;
            int cl = wn * 16 + nt * 8 + (lane & 3) * 2;
            float q0 = (float)(qb + r0), q8 = q0 + 8.0f;
            float k0f = (float)(kc + cl), k1f = k0f + 1.0f;
            *(float2*)&sS[r0 * SSST + kc + cl] = make_float2(
                cr[nt][0] * scale - slope * fabsf(q0 - k0f),
                cr[nt][1] * scale - slope * fabsf(q0 - k1f));
            *(float2*)&sS[(r0 + 8) * SSST + kc + cl] = make_float2(
                cr[nt][2] * scale - slope * fabsf(q8 - k0f),
                cr[nt][3] * scale - slope * fabsf(q8 - k1f));
        }
        __syncthreads();
        buf ^= 1;
    }

    // prefetch V chunks 0 and 1 (overlaps softmax)
    issueKV(Vb, 0, 0);
    issueKV(Vb, 1, 1);

    // ---- softmax (two passes; P fp16 overwrites sS in place) ----
    // Pass p: warp w owns row p*8+w. P row q at half offset q*PHST.
    // Pass 0 P-writes (bytes < 16.8K) never touch fp32 rows 8-15 (>= 32.9K);
    // Pass 1 P-writes only clobber fp32 bytes already consumed.
    const size_t attn_base = (((size_t)(b * HH + h)) * TT + qb) * TT;
    __half* sSh = (__half*)sS;
    #pragma unroll
    for (int pass = 0; pass < 2; pass++) {
        int q = pass * 8 + warp;
        float* row = sS + q * SSST;
        float4 e[8];
        float m = -1e30f;
        #pragma unroll
        for (int it = 0; it < 8; it++) {
            e[it] = *(float4*)(row + it * 128 + lane * 4);
            m = fmaxf(m, fmaxf(fmaxf(e[it].x, e[it].y), fmaxf(e[it].z, e[it].w)));
        }
        #pragma unroll
        for (int off = 16; off; off >>= 1) m = fmaxf(m, __shfl_xor_sync(~0u, m, off));
        float s = 0.f;
        #pragma unroll
        for (int it = 0; it < 8; it++) {
            e[it].x = __expf(e[it].x - m);
            e[it].y = __expf(e[it].y - m);
            e[it].z = __expf(e[it].z - m);
            e[it].w = __expf(e[it].w - m);
            s += (e[it].x + e[it].y) + (e[it].z + e[it].w);
        }
        #pragma unroll
        for (int off = 16; off; off >>= 1) s += __shfl_xor_sync(~0u, s, off);
        float inv = 1.0f / s;

        __syncthreads();   // all warps done reading this pass's fp32 rows

        float*  out = attn + attn_base + (size_t)q * TT;
        __half* ph  = sSh + q * PHST;
        #pragma unroll
        for (int it = 0; it < 8; it++) {
            float4 v = e[it];
            v.x *= inv; v.y *= inv; v.z *= inv; v.w *= inv;
            int cx = it * 128 + lane * 4;
            *(float4*)(out + cx) = v;            // fp32 attn output
            *(uint2*)(ph + cx)   = f4_to_h4(v);  // fp16 P in smem
        }
    }
    __syncthreads();       // P fully published before PV reads

    // ---- PV phase: Y[16x64] = P @ V, 8 chunks of 128 V-rows ----
    float yacc[4] = {0.f, 0.f, 0.f, 0.f};
    const int nbase = (warp >> 1) * 16;    // n16 group shared by warp pair
    const int nsel  = warp & 1;            // which n8 half of the x4t load
    const uint32_t voff = (uint32_t)((lane & 15) * KST + nbase + lkof) * 2;

    for (int c = 0; c < 8; c++) {
        if (c < 7) { CPWAIT(1); } else { CPWAIT(0); }
        __syncthreads();

        const uint32_t VU = sKu + (c & 1) * KBUFB;
        #pragma unroll
        for (int ks = 0; ks < 8; ks++) {
            uint32_t a[4], bf[4];
            uint32_t paddr = sSu +
                (uint32_t)((lane & 15) * PHST + c * 128 + ks * 16 + lkof) * 2;
            ldsm_x4(a[0], a[1], a[2], a[3], paddr);
            ldsm_x4t(bf[0], bf[1], bf[2], bf[3], VU + voff + ks * 16 * (KST * 2));
            mma_f16(yacc, a, bf + nsel * 2);
        }
        __syncthreads();   // reads done before refilling this buffer

        if (c + 2 < 8) issueKV(Vb, c + 2, c & 1);
    }

    // Y store (fp16: feeds the output projection)
    {
        int r0 = qb + (lane >> 2);
        int c0 = h * DD + warp * 8 + (lane & 3) * 2;
        __half2 h01 = __floats2half2_rn(yacc[0], yacc[1]);
        __half2 h23 = __floats2half2_rn(yacc[2], yacc[3]);
        *(__half2*)&Y[(size_t)(b * TT + r0) * CC + c0]     = h01;
        *(__half2*)&Y[(size_t)(b * TT + r0 + 8) * CC + c0] = h23;
    }
}

// ---------------------------------------------------------------------------
// launch: prepass -> QKV proj -> fused attention -> output proj
// d_out = [ y (B*T*C) fp32 | attn (B*H*T*T) fp32 ]
// ---------------------------------------------------------------------------
extern "C" void kernel_launch(void* const* d_in, const int* in_sizes, int n_in,
                              void* d_out, int out_size)
{
    const float* x  = (const float*)d_in[0];
    const float* Wq = (const float*)d_in[1];
    const float* Wk = (const float*)d_in[2];
    const float* Wv = (const float*)d_in[3];
    const float* Wp = (const float*)d_in[4];

    float* out      = (float*)d_out;
    float* y_out    = out;
    float* attn_out = out + (size_t)BB * TT * CC;

    __half *Qh, *Kh, *Vh, *Yh, *Xh, *Wh;
    cudaGetSymbolAddress((void**)&Qh, g_Qh);
    cudaGetSymbolAddress((void**)&Kh, g_Kh);
    cudaGetSymbolAddress((void**)&Vh, g_Vh);
    cudaGetSymbolAddress((void**)&Yh, g_Yh);
    cudaGetSymbolAddress((void**)&Xh, g_Xh);
    cudaGetSymbolAddress((void**)&Wh, g_Wh);

    prepass<<<dim3(1024, 5), 256>>>(x, Wq, Wk, Wv, Wp);

    const size_t gemm_smem = (size_t)8 * GSTG;                        // 81920
    cudaFuncSetAttribute(gemm_f16_nt,
                         cudaFuncAttributeMaxDynamicSharedMemorySize,
                         (int)gemm_smem);

    dim3 gq(CC / 128, BT / 128, 3);
    gemm_f16_nt<<<gq, 512, gemm_smem>>>(Xh, Wh, Qh, Kh, Vh, nullptr, 1);

    const size_t fused_smem =
        (size_t)QT * SSST * 4 + QT * QST * 2 + 2 * KBUFB;             // 104960
    cudaFuncSetAttribute(attn_fused_kernel,
                         cudaFuncAttributeMaxDynamicSharedMemorySize,
                         (int)fused_smem);
    attn_fused_kernel<<<dim3(TT / QT, HH, BB), 256, fused_smem>>>(
        Qh, Kh, Vh, attn_out, Yh);

    dim3 gp(CC / 128, BT / 128, 1);
    gemm_f16_nt<<<gp, 512, gemm_smem>>>(Yh, Wh + (size_t)3 * CC * CC,
                                        nullptr, nullptr, nullptr, y_out, 0);
}

// round 12
// speedup vs baseline: 1.2648x; 1.2648x over previous
#include <cuda_runtime.h>
#include <cuda_fp16.h>
#include <math.h>
#include <stdint.h>

#define BB   4
#define TT   1024
#define CC   1024
#define HH   16
#define DD   64
#define BT   (BB*TT)          // 4096

// Scratch (allocation-free rule: __device__ globals)
__device__ __half g_Qh[BT * CC];
__device__ __half g_Kh[BT * CC];
__device__ __half g_Vh[BT * CC];
__device__ __half g_Yh[BT * CC];
__device__ __half g_Xh[BT * CC];          // fp16-rounded x
__device__ __half g_Wh[4 * CC * CC];      // fp16-rounded Wq|Wk|Wv|Wp
__device__ __half g_P[(size_t)BB * HH * TT * TT];   // fp16 attention probs

// ---------------------------------------------------------------------------
// helpers
// ---------------------------------------------------------------------------
__device__ __forceinline__ uint2 f4_to_h4(float4 v) {
    __half2 a = __floats2half2_rn(v.x, v.y);
    __half2 b = __floats2half2_rn(v.z, v.w);
    uint2 r;
    r.x = *(uint32_t*)&a;
    r.y = *(uint32_t*)&b;
    return r;
}

__device__ __forceinline__ void mma_f16(float* c, const uint32_t* a, const uint32_t* b) {
    asm volatile(
        "mma.sync.aligned.m16n8k16.row.col.f32.f16.f16.f32 "
        "{%0,%1,%2,%3}, {%4,%5,%6,%7}, {%8,%9}, {%0,%1,%2,%3};"
        : "+f"(c[0]), "+f"(c[1]), "+f"(c[2]), "+f"(c[3])
        : "r"(a[0]), "r"(a[1]), "r"(a[2]), "r"(a[3]), "r"(b[0]), "r"(b[1]));
}

__device__ __forceinline__ void ldsm_x4(uint32_t& r0, uint32_t& r1,
                                        uint32_t& r2, uint32_t& r3, uint32_t addr) {
    asm volatile("ldmatrix.sync.aligned.m8n8.x4.shared.b16 {%0,%1,%2,%3}, [%4];"
                 : "=r"(r0), "=r"(r1), "=r"(r2), "=r"(r3) : "r"(addr));
}
__device__ __forceinline__ void ldsm_x4t(uint32_t& r0, uint32_t& r1,
                                         uint32_t& r2, uint32_t& r3, uint32_t addr) {
    asm volatile("ldmatrix.sync.aligned.m8n8.x4.trans.shared.b16 {%0,%1,%2,%3}, [%4];"
                 : "=r"(r0), "=r"(r1), "=r"(r2), "=r"(r3) : "r"(addr));
}

#define CPA16(dst_u32, src_ptr) \
    asm volatile("cp.async.cg.shared.global [%0], [%1], 16;" \
                 :: "r"(dst_u32), "l"(src_ptr))
#define CPCOMMIT() asm volatile("cp.async.commit_group;")
#define CPWAIT(n)  asm volatile("cp.async.wait_group %0;" :: "n"(n))

// ---------------------------------------------------------------------------
// prepass: fp16-round x -> g_Xh, weights -> g_Wh (concat)
// ---------------------------------------------------------------------------
__global__ void prepass(const float* __restrict__ x,
                        const float* __restrict__ wq, const float* __restrict__ wk,
                        const float* __restrict__ wv, const float* __restrict__ wp)
{
    int which = blockIdx.y;
    const float* src;
    __half* dst;
    int n4;
    if (which == 0) { src = x;  dst = g_Xh; n4 = BT * CC / 4; }
    else {
        src = (which == 1) ? wq : (which == 2) ? wk : (which == 3) ? wv : wp;
        dst = g_Wh + (size_t)(which - 1) * CC * CC;
        n4 = CC * CC / 4;
    }
    for (int i = blockIdx.x * blockDim.x + threadIdx.x; i < n4;
         i += gridDim.x * blockDim.x) {
        float4 v = ((const float4*)src)[i];
        ((uint2*)dst)[i] = f4_to_h4(v);
    }
}

// ---------------------------------------------------------------------------
// C[M,N] = A[M,K] @ W[N,K]^T, FP16 MMA m16n8k16, inputs pre-rounded fp16.
// CTA tile 128x256, warp tile 32x64 (16 warps, 512 thr), BK=32, 4-stage
// cp.async, ldmatrix fragments. 2.67 MMA/LDSM.
// ro=1: write half outputs H0/H1/H2 (per blockIdx.z); ro=0: float C0.
// ---------------------------------------------------------------------------
#define AST 40                    // halfs per row (80 bytes)
#define ASTGB (128 * AST * 2)     // A stage bytes: 10240
#define BSTGB (256 * AST * 2)     // B stage bytes: 20480
#define NTG 32                    // K/32
__global__ __launch_bounds__(512, 1)
void gemm_f16_nt(const __half* __restrict__ A, const __half* __restrict__ Wb,
                 __half* __restrict__ H0, __half* __restrict__ H1,
                 __half* __restrict__ H2, float* __restrict__ C0, int ro)
{
    const __half* Bw = Wb + (size_t)blockIdx.z * CC * CC;
    __half* H = (blockIdx.z == 0) ? H0 : (blockIdx.z == 1 ? H1 : H2);

    extern __shared__ char smraw[];
    uint32_t sAu = (uint32_t)__cvta_generic_to_shared(smraw);
    uint32_t sBu = sAu + 4 * ASTGB;

    const int tid  = threadIdx.x;
    const int lane = tid & 31;
    const int warp = tid >> 5;
    const int wm   = (warp & 3) * 32;     // 4 m-groups of 32
    const int wn   = (warp >> 2) * 64;    // 4 n-groups of 64

    const int lrow = lane & 15;
    const int lkof = (lane & 16) ? 8 : 0;     // halfs
    const uint32_t aoff0 = ((wm + lrow)      * AST + lkof) * 2;
    const uint32_t aoff1 = ((wm + 16 + lrow) * AST + lkof) * 2;
    uint32_t boff[4];
    #pragma unroll
    for (int j = 0; j < 4; j++)
        boff[j] = ((wn + j * 16 + lrow) * AST + lkof) * 2;

    const __half* Abase = A  + (size_t)(blockIdx.y * 128) * CC;
    const __half* Bbase = Bw + (size_t)(blockIdx.x * 256) * CC;

    auto load_stage = [&](int kt, int s) {
        {   // A: 512 granules (128 rows x 4)
            int row = tid >> 2, seg = tid & 3;
            CPA16(sAu + s * ASTGB + row * 80 + seg * 16,
                  Abase + (size_t)row * CC + kt * 32 + seg * 8);
        }
        #pragma unroll
        for (int i = 0; i < 2; i++) {   // B: 1024 granules (256 rows x 4)
            int g = tid + i * 512;
            int row = g >> 2, seg = g & 3;
            CPA16(sBu + s * BSTGB + row * 80 + seg * 16,
                  Bbase + (size_t)row * CC + kt * 32 + seg * 8);
        }
        CPCOMMIT();
    };

    load_stage(0, 0);
    load_stage(1, 1);
    load_stage(2, 2);

    float acc[2][8][4];
    #pragma unroll
    for (int i = 0; i < 2; i++)
        #pragma unroll
        for (int j = 0; j < 8; j++)
            #pragma unroll
            for (int k = 0; k < 4; k++) acc[i][j][k] = 0.f;

    for (int kt = 0; kt < NTG; kt++) {
        if (kt <= NTG - 3)      { CPWAIT(2); }
        else if (kt == NTG - 2) { CPWAIT(1); }
        else                    { CPWAIT(0); }
        __syncthreads();

        if (kt + 3 < NTG) load_stage(kt + 3, (kt + 3) & 3);

        const uint32_t AbU = sAu + (kt & 3) * ASTGB;
        const uint32_t BbU = sBu + (kt & 3) * BSTGB;

        #pragma unroll
        for (int ks = 0; ks < 2; ks++) {                 // 2 x k16
            uint32_t af[2][4], bf[8][2];
            ldsm_x4(af[0][0], af[0][1], af[0][2], af[0][3], AbU + aoff0 + ks * 32);
            ldsm_x4(af[1][0], af[1][1], af[1][2], af[1][3], AbU + aoff1 + ks * 32);
            #pragma unroll
            for (int j = 0; j < 4; j++)
                ldsm_x4(bf[2 * j][0], bf[2 * j + 1][0],
                        bf[2 * j][1], bf[2 * j + 1][1], BbU + boff[j] + ks * 32);
            #pragma unroll
            for (int mt = 0; mt < 2; mt++)
                #pragma unroll
                for (int nt = 0; nt < 8; nt++)
                    mma_f16(acc[mt][nt], af[mt], bf[nt]);
        }
    }

    #pragma unroll
    for (int mt = 0; mt < 2; mt++) {
        int r0 = blockIdx.y * 128 + wm + mt * 16 + (lane >> 2);
        #pragma unroll
        for (int nt = 0; nt < 8; nt++) {
            int c0 = blockIdx.x * 256 + wn + nt * 8 + (lane & 3) * 2;
            if (ro) {
                __half2 h01 = __floats2half2_rn(acc[mt][nt][0], acc[mt][nt][1]);
                __half2 h23 = __floats2half2_rn(acc[mt][nt][2], acc[mt][nt][3]);
                *(__half2*)&H[(size_t)r0 * CC + c0]       = h01;
                *(__half2*)&H[(size_t)(r0 + 8) * CC + c0] = h23;
            } else {
                *(float2*)&C0[(size_t)r0 * CC + c0] =
                    make_float2(acc[mt][nt][0], acc[mt][nt][1]);
                *(float2*)&C0[(size_t)(r0 + 8) * CC + c0] =
                    make_float2(acc[mt][nt][2], acc[mt][nt][3]);
            }
        }
    }
}

// ---------------------------------------------------------------------------
// Kernel A: scores + ALiBi + softmax; writes attn fp32 (d_out) + P fp16 (g_P).
// block=(b,h,16q), 256 thr, 2 CTAs/SM. (R10 configuration — known good.)
// ---------------------------------------------------------------------------
#define QT   16
#define SSST 1028
#define QST 72
#define KST 72
#define KBUFB (128 * KST * 2)    // stage bytes: 18432
__global__ __launch_bounds__(256, 2)
void attn_score_kernel(const __half* __restrict__ Q, const __half* __restrict__ Km,
                       float* __restrict__ attn, __half* __restrict__ Ph)
{
    extern __shared__ char smraw[];
    float*  sS = (float*)smraw;                        // QT*1028 floats
    __half* sQ = (__half*)(smraw + QT * SSST * 4);     // QT*72 halfs
    char*   sK = smraw + QT * SSST * 4 + QT * QST * 2; // 2 * KBUFB
    uint32_t sQu = (uint32_t)__cvta_generic_to_shared(sQ);
    uint32_t sKu = (uint32_t)__cvta_generic_to_shared(sK);

    const int tid  = threadIdx.x;
    const int lane = tid & 31;
    const int warp = tid >> 5;           // 0..7
    const int qb   = blockIdx.x * QT;
    const int h    = blockIdx.y;
    const int b    = blockIdx.z;

    const float scale = 0.125f;
    const float slope = exp2f(-0.5f * (float)(h + 1));

    const int wn = warp;                 // 16-col chunk per warp

    const int lrow = lane & 15;
    const int lkof = (lane & 16) ? 8 : 0;
    const uint32_t koff = ((wn * 16 + lrow) * KST + lkof) * 2;

    const __half* Kb = Km + ((size_t)(b * TT)) * CC + h * DD;

    auto issueK = [&](int c, int buf) {
        const __half* base = Kb + (size_t)(c * 128) * CC;
        #pragma unroll
        for (int i = 0; i < 4; i++) {
            int g = tid + i * 256;              // 1024 granules
            int row = g >> 3, seg = g & 7;
            CPA16(sKu + buf * KBUFB + row * (KST * 2) + seg * 16,
                  base + (size_t)row * CC + seg * 8);
        }
        CPCOMMIT();
    };

    issueK(0, 0);

    // Q tile [16 x 64] halfs -> sQ
    if (tid < 128) {
        const __half* Qb = Q + ((size_t)(b * TT + qb)) * CC + h * DD;
        int r = tid >> 3, seg = tid & 7;
        *(uint4*)(sQ + r * QST + seg * 8) =
            *(const uint4*)(Qb + (size_t)r * CC + seg * 8);
    }
    __syncthreads();

    // preload Q fragments for all 4 k16-steps (loop-invariant; m16 = all QT rows)
    uint32_t aq[4][4];
    {
        uint32_t qoff = sQu + (lrow * QST + lkof) * 2;
        #pragma unroll
        for (int ks = 0; ks < 4; ks++)
            ldsm_x4(aq[ks][0], aq[ks][1], aq[ks][2], aq[ks][3], qoff + ks * 32);
    }

    int buf = 0;
    for (int c = 0; c < 8; c++) {
        if (c + 1 < 8) issueK(c + 1, buf ^ 1);
        if (c < 7) { CPWAIT(1); } else { CPWAIT(0); }
        __syncthreads();

        const uint32_t KU = sKu + buf * KBUFB;
        float cr[2][4];
        #pragma unroll
        for (int nt = 0; nt < 2; nt++)
            #pragma unroll
            for (int i = 0; i < 4; i++) cr[nt][i] = 0.f;

        #pragma unroll
        for (int ks = 0; ks < 4; ks++) {
            uint32_t bf2[2][2];
            ldsm_x4(bf2[0][0], bf2[1][0], bf2[0][1], bf2[1][1], KU + koff + ks * 32);
            mma_f16(cr[0], aq[ks], bf2[0]);
            mma_f16(cr[1], aq[ks], bf2[1]);
        }

        const int kc = c * 128;
        #pragma unroll
        for (int nt = 0; nt < 2; nt++) {
            int r0 = lane >> 2;
            int cl = wn * 16 + nt * 8 + (lane & 3) * 2;
            float q0 = (float)(qb + r0), q8 = q0 + 8.0f;
            float k0f = (float)(kc + cl), k1f = k0f + 1.0f;
            *(float2*)&sS[r0 * SSST + kc + cl] = make_float2(
                cr[nt][0] * scale - slope * fabsf(q0 - k0f),
                cr[nt][1] * scale - slope * fabsf(q0 - k1f));
            *(float2*)&sS[(r0 + 8) * SSST + kc + cl] = make_float2(
                cr[nt][2] * scale - slope * fabsf(q8 - k0f),
                cr[nt][3] * scale - slope * fabsf(q8 - k1f));
        }
        __syncthreads();
        buf ^= 1;
    }

    // softmax: each warp owns 2 rows; write attn fp32 + P fp16
    const size_t attn_base = (((size_t)(b * HH + h)) * TT + qb) * TT;
    #pragma unroll
    for (int rr = 0; rr < 2; rr++) {
        int q = warp * 2 + rr;
        float* row = sS + q * SSST;
        float4 e[8];
        float m = -1e30f;
        #pragma unroll
        for (int it = 0; it < 8; it++) {
            e[it] = *(float4*)(row + it * 128 + lane * 4);
            m = fmaxf(m, fmaxf(fmaxf(e[it].x, e[it].y), fmaxf(e[it].z, e[it].w)));
        }
        #pragma unroll
        for (int off = 16; off; off >>= 1) m = fmaxf(m, __shfl_xor_sync(~0u, m, off));
        float s = 0.f;
        #pragma unroll
        for (int it = 0; it < 8; it++) {
            e[it].x = __expf(e[it].x - m);
            e[it].y = __expf(e[it].y - m);
            e[it].z = __expf(e[it].z - m);
            e[it].w = __expf(e[it].w - m);
            s += (e[it].x + e[it].y) + (e[it].z + e[it].w);
        }
        #pragma unroll
        for (int off = 16; off; off >>= 1) s += __shfl_xor_sync(~0u, s, off);
        float inv = 1.0f / s;
        float*  out  = attn + attn_base + (size_t)q * TT;
        __half* outh = Ph + attn_base + (size_t)q * TT;
        #pragma unroll
        for (int it = 0; it < 8; it++) {
            float4 v = e[it];
            v.x *= inv; v.y *= inv; v.z *= inv; v.w *= inv;
            int cx = it * 128 + lane * 4;
            *(float4*)(out + cx) = v;            // fp32 attn output
            *(uint2*)(outh + cx) = f4_to_h4(v);  // fp16 P for PV
        }
    }
}

// ---------------------------------------------------------------------------
// Kernel B: Y[128x64] = P[128x1024] @ V[1024x64] per (b,h,qtile), all fp16.
// 256 thr, 4-stage cp.async, P via ldmatrix, V via ldmatrix.trans.
// (R10 configuration — known good.)
// ---------------------------------------------------------------------------
#define PST 40
#define VST 72
#define PSTGB (128 * PST * 2)     // 10240
#define VSTGB (32 * VST * 2)      // 4608
__global__ __launch_bounds__(256, 2)
void pv_kernel(const __half* __restrict__ Ph, const __half* __restrict__ V,
               __half* __restrict__ Y)
{
    extern __shared__ char smraw[];
    uint32_t sPu = (uint32_t)__cvta_generic_to_shared(smraw);
    uint32_t sVu = sPu + 4 * PSTGB;

    const int tid  = threadIdx.x;
    const int lane = tid & 31;
    const int warp = tid >> 5;            // 0..7
    const int qb   = blockIdx.x * 128;
    const int h    = blockIdx.y;
    const int b    = blockIdx.z;

    const int wm = (warp >> 1) * 32;
    const int wn = (warp & 1) * 32;

    const int lrow = lane & 15;
    const int lkof = (lane & 16) ? 8 : 0;
    const uint32_t poff0 = ((wm + lrow)      * PST + lkof) * 2;
    const uint32_t poff1 = ((wm + 16 + lrow) * PST + lkof) * 2;
    const uint32_t voff = ((lane & 15) * VST + wn + lkof) * 2;

    const __half* Pb = Ph + (((size_t)(b * HH + h)) * TT + qb) * TT;
    const __half* Vb = V + ((size_t)(b * TT)) * CC + h * DD;

    auto load_stage = [&](int kt, int s) {
        #pragma unroll
        for (int i = 0; i < 2; i++) {
            int g = tid + i * 256;               // 512 P granules
            int row = g >> 2, seg = g & 3;
            CPA16(sPu + s * PSTGB + row * 80 + seg * 16,
                  Pb + (size_t)row * TT + kt * 32 + seg * 8);
        }
        {
            int row = tid >> 3, seg = tid & 7;   // 256 V granules
            CPA16(sVu + s * VSTGB + row * (VST * 2) + seg * 16,
                  Vb + (size_t)(kt * 32 + row) * CC + seg * 8);
        }
        CPCOMMIT();
    };

    load_stage(0, 0);
    load_stage(1, 1);
    load_stage(2, 2);

    float acc[2][4][4];
    #pragma unroll
    for (int i = 0; i < 2; i++)
        #pragma unroll
        for (int j = 0; j < 4; j++)
            #pragma unroll
            for (int k = 0; k < 4; k++) acc[i][j][k] = 0.f;

    const int NT2 = 32;
    for (int kt = 0; kt < NT2; kt++) {
        if (kt <= NT2 - 3)      { CPWAIT(2); }
        else if (kt == NT2 - 2) { CPWAIT(1); }
        else                    { CPWAIT(0); }
        __syncthreads();

        if (kt + 3 < NT2) load_stage(kt + 3, (kt + 3) & 3);

        const uint32_t PtU = sPu + (kt & 3) * PSTGB;
        const uint32_t VtU = sVu + (kt & 3) * VSTGB;

        #pragma unroll
        for (int ks = 0; ks < 2; ks++) {
            uint32_t af[2][4], bf[4][2];
            ldsm_x4(af[0][0], af[0][1], af[0][2], af[0][3], PtU + poff0 + ks * 32);
            ldsm_x4(af[1][0], af[1][1], af[1][2], af[1][3], PtU + poff1 + ks * 32);
            ldsm_x4t(bf[0][0], bf[0][1], bf[1][0], bf[1][1],
                     VtU + voff + ks * 16 * (VST * 2));
            ldsm_x4t(bf[2][0], bf[2][1], bf[3][0], bf[3][1],
                     VtU + voff + 16 * 2 + ks * 16 * (VST * 2));
            #pragma unroll
            for (int mt2 = 0; mt2 < 2; mt2++)
                #pragma unroll
                for (int nt = 0; nt < 4; nt++)
                    mma_f16(acc[mt2][nt], af[mt2], bf[nt]);
        }
    }

    #pragma unroll
    for (int mt2 = 0; mt2 < 2; mt2++) {
        int r0 = qb + wm + mt2 * 16 + (lane >> 2);
        #pragma unroll
        for (int nt = 0; nt < 4; nt++) {
            int c0 = wn + nt * 8 + (lane & 3) * 2;
            __half2 h01 = __floats2half2_rn(acc[mt2][nt][0], acc[mt2][nt][1]);
            __half2 h23 = __floats2half2_rn(acc[mt2][nt][2], acc[mt2][nt][3]);
            *(__half2*)&Y[(size_t)(b * TT + r0) * CC + h * DD + c0]       = h01;
            *(__half2*)&Y[(size_t)(b * TT + r0 + 8) * CC + h * DD + c0]   = h23;
        }
    }
}

// ---------------------------------------------------------------------------
// launch: prepass -> QKV proj -> scores/softmax -> PV -> output proj
// d_out = [ y (B*T*C) fp32 | attn (B*H*T*T) fp32 ]
// ---------------------------------------------------------------------------
extern "C" void kernel_launch(void* const* d_in, const int* in_sizes, int n_in,
                              void* d_out, int out_size)
{
    const float* x  = (const float*)d_in[0];
    const float* Wq = (const float*)d_in[1];
    const float* Wk = (const float*)d_in[2];
    const float* Wv = (const float*)d_in[3];
    const float* Wp = (const float*)d_in[4];

    float* out      = (float*)d_out;
    float* y_out    = out;
    float* attn_out = out + (size_t)BB * TT * CC;

    __half *Qh, *Kh, *Vh, *Yh, *Xh, *Wh, *Pp;
    cudaGetSymbolAddress((void**)&Qh, g_Qh);
    cudaGetSymbolAddress((void**)&Kh, g_Kh);
    cudaGetSymbolAddress((void**)&Vh, g_Vh);
    cudaGetSymbolAddress((void**)&Yh, g_Yh);
    cudaGetSymbolAddress((void**)&Xh, g_Xh);
    cudaGetSymbolAddress((void**)&Wh, g_Wh);
    cudaGetSymbolAddress((void**)&Pp, g_P);

    prepass<<<dim3(1024, 5), 256>>>(x, Wq, Wk, Wv, Wp);

    const size_t gemm_smem = (size_t)4 * (ASTGB + BSTGB);             // 122880
    cudaFuncSetAttribute(gemm_f16_nt,
                         cudaFuncAttributeMaxDynamicSharedMemorySize,
                         (int)gemm_smem);

    dim3 gq(CC / 256, BT / 128, 3);
    gemm_f16_nt<<<gq, 512, gemm_smem>>>(Xh, Wh, Qh, Kh, Vh, nullptr, 1);

    const size_t scoreA_smem =
        (size_t)QT * SSST * 4 + QT * QST * 2 + 2 * KBUFB;             // 104960
    cudaFuncSetAttribute(attn_score_kernel,
                         cudaFuncAttributeMaxDynamicSharedMemorySize,
                         (int)scoreA_smem);
    attn_score_kernel<<<dim3(TT / QT, HH, BB), 256, scoreA_smem>>>(
        Qh, Kh, attn_out, Pp);

    const size_t pv_smem = (size_t)4 * (PSTGB + VSTGB);               // 59392
    cudaFuncSetAttribute(pv_kernel,
                         cudaFuncAttributeMaxDynamicSharedMemorySize,
                         (int)pv_smem);
    pv_kernel<<<dim3(TT / 128, HH, BB), 256, pv_smem>>>(Pp, Vh, Yh);

    dim3 gp(CC / 256, BT / 128, 1);
    gemm_f16_nt<<<gp, 512, gemm_smem>>>(Yh, Wh + (size_t)3 * CC * CC,
                                        nullptr, nullptr, nullptr, y_out, 0);
}

// round 13
// speedup vs baseline: 1.2748x; 1.0079x over previous
#include <cuda_runtime.h>
#include <cuda_fp16.h>
#include <math.h>
#include <stdint.h>

#define BB   4
#define TT   1024
#define CC   1024
#define HH   16
#define DD   64
#define BT   (BB*TT)          // 4096

// Scratch (allocation-free rule: __device__ globals)
__device__ __half g_Qh[BT * CC];
__device__ __half g_Kh[BT * CC];
__device__ __half g_Vh[BT * CC];
__device__ __half g_Yh[BT * CC];
__device__ __half g_Xh[BT * CC];          // fp16-rounded x
__device__ __half g_Wh[4 * CC * CC];      // fp16-rounded Wq|Wk|Wv|Wp
__device__ __half g_P[(size_t)BB * HH * TT * TT];   // fp16 attention probs

// ---------------------------------------------------------------------------
// helpers
// ---------------------------------------------------------------------------
__device__ __forceinline__ uint2 f4_to_h4(float4 v) {
    __half2 a = __floats2half2_rn(v.x, v.y);
    __half2 b = __floats2half2_rn(v.z, v.w);
    uint2 r;
    r.x = *(uint32_t*)&a;
    r.y = *(uint32_t*)&b;
    return r;
}

__device__ __forceinline__ void mma_f16(float* c, const uint32_t* a, const uint32_t* b) {
    asm volatile(
        "mma.sync.aligned.m16n8k16.row.col.f32.f16.f16.f32 "
        "{%0,%1,%2,%3}, {%4,%5,%6,%7}, {%8,%9}, {%0,%1,%2,%3};"
        : "+f"(c[0]), "+f"(c[1]), "+f"(c[2]), "+f"(c[3])
        : "r"(a[0]), "r"(a[1]), "r"(a[2]), "r"(a[3]), "r"(b[0]), "r"(b[1]));
}

__device__ __forceinline__ void ldsm_x4(uint32_t& r0, uint32_t& r1,
                                        uint32_t& r2, uint32_t& r3, uint32_t addr) {
    asm volatile("ldmatrix.sync.aligned.m8n8.x4.shared.b16 {%0,%1,%2,%3}, [%4];"
                 : "=r"(r0), "=r"(r1), "=r"(r2), "=r"(r3) : "r"(addr));
}
__device__ __forceinline__ void ldsm_x4t(uint32_t& r0, uint32_t& r1,
                                         uint32_t& r2, uint32_t& r3, uint32_t addr) {
    asm volatile("ldmatrix.sync.aligned.m8n8.x4.trans.shared.b16 {%0,%1,%2,%3}, [%4];"
                 : "=r"(r0), "=r"(r1), "=r"(r2), "=r"(r3) : "r"(addr));
}

#define CPA16(dst_u32, src_ptr) \
    asm volatile("cp.async.cg.shared.global [%0], [%1], 16;" \
                 :: "r"(dst_u32), "l"(src_ptr))
#define CPCOMMIT() asm volatile("cp.async.commit_group;")
#define CPWAIT(n)  asm volatile("cp.async.wait_group %0;" :: "n"(n))

// ---------------------------------------------------------------------------
// prepass: fp16-round x -> g_Xh, weights -> g_Wh (concat)
// ---------------------------------------------------------------------------
__global__ void prepass(const float* __restrict__ x,
                        const float* __restrict__ wq, const float* __restrict__ wk,
                        const float* __restrict__ wv, const float* __restrict__ wp)
{
    int which = blockIdx.y;
    const float* src;
    __half* dst;
    int n4;
    if (which == 0) { src = x;  dst = g_Xh; n4 = BT * CC / 4; }
    else {
        src = (which == 1) ? wq : (which == 2) ? wk : (which == 3) ? wv : wp;
        dst = g_Wh + (size_t)(which - 1) * CC * CC;
        n4 = CC * CC / 4;
    }
    for (int i = blockIdx.x * blockDim.x + threadIdx.x; i < n4;
         i += gridDim.x * blockDim.x) {
        float4 v = ((const float4*)src)[i];
        ((uint2*)dst)[i] = f4_to_h4(v);
    }
}

// ---------------------------------------------------------------------------
// C[M,N] = A[M,K] @ W[N,K]^T, FP16 MMA m16n8k16, inputs pre-rounded fp16.
// 128x128 tile, BK=64 (16 barriers instead of 32), 512 threads, 4-stage
// cp.async, ldmatrix fragments (row stride 72 halfs: conflict-free phases).
// ro=1: write half outputs H0/H1/H2 (per blockIdx.z); ro=0: float C0.
// ---------------------------------------------------------------------------
#define AST 72                    // halfs per row (144 bytes)
#define GSTG (128 * AST * 2)      // stage bytes per array: 18432
#define NTG 16                    // K/64
__global__ __launch_bounds__(512, 1)
void gemm_f16_nt(const __half* __restrict__ A, const __half* __restrict__ Wb,
                 __half* __restrict__ H0, __half* __restrict__ H1,
                 __half* __restrict__ H2, float* __restrict__ C0, int ro)
{
    const __half* Bw = Wb + (size_t)blockIdx.z * CC * CC;
    __half* H = (blockIdx.z == 0) ? H0 : (blockIdx.z == 1 ? H1 : H2);

    extern __shared__ char smraw[];
    uint32_t sAu = (uint32_t)__cvta_generic_to_shared(smraw);
    uint32_t sBu = sAu + 4 * GSTG;

    const int tid  = threadIdx.x;
    const int lane = tid & 31;
    const int warp = tid >> 5;
    const int wm   = (warp & 3) * 32;
    const int wn   = (warp >> 2) * 32;

    const int lrow = lane & 15;
    const int lkof = (lane & 16) ? 8 : 0;     // halfs
    const uint32_t aoff0 = ((wm + lrow)      * AST + lkof) * 2;
    const uint32_t aoff1 = ((wm + 16 + lrow) * AST + lkof) * 2;
    const uint32_t boff0 = ((wn + lrow)      * AST + lkof) * 2;
    const uint32_t boff1 = ((wn + 16 + lrow) * AST + lkof) * 2;

    const __half* Abase = A  + (size_t)(blockIdx.y * 128) * CC;
    const __half* Bbase = Bw + (size_t)(blockIdx.x * 128) * CC;

    auto load_stage = [&](int kt, int s) {
        #pragma unroll
        for (int i = 0; i < 2; i++) {
            int g = tid + i * 512;                 // 1024 granules per array
            int row = g >> 3, seg = g & 7;
            CPA16(sAu + s * GSTG + row * (AST * 2) + seg * 16,
                  Abase + (size_t)row * CC + kt * 64 + seg * 8);
            CPA16(sBu + s * GSTG + row * (AST * 2) + seg * 16,
                  Bbase + (size_t)row * CC + kt * 64 + seg * 8);
        }
        CPCOMMIT();
    };

    load_stage(0, 0);
    load_stage(1, 1);
    load_stage(2, 2);

    float acc[2][4][4];
    #pragma unroll
    for (int i = 0; i < 2; i++)
        #pragma unroll
        for (int j = 0; j < 4; j++)
            #pragma unroll
            for (int k = 0; k < 4; k++) acc[i][j][k] = 0.f;

    for (int kt = 0; kt < NTG; kt++) {
        if (kt <= NTG - 3)      { CPWAIT(2); }
        else if (kt == NTG - 2) { CPWAIT(1); }
        else                    { CPWAIT(0); }
        __syncthreads();

        if (kt + 3 < NTG) load_stage(kt + 3, (kt + 3) & 3);

        const uint32_t AbU = sAu + (kt & 3) * GSTG;
        const uint32_t BbU = sBu + (kt & 3) * GSTG;

        #pragma unroll
        for (int ks = 0; ks < 4; ks++) {                 // 4 x k16
            uint32_t af[2][4], bf[4][2];
            ldsm_x4(af[0][0], af[0][1], af[0][2], af[0][3], AbU + aoff0 + ks * 32);
            ldsm_x4(af[1][0], af[1][1], af[1][2], af[1][3], AbU + aoff1 + ks * 32);
            ldsm_x4(bf[0][0], bf[1][0], bf[0][1], bf[1][1], BbU + boff0 + ks * 32);
            ldsm_x4(bf[2][0], bf[3][0], bf[2][1], bf[3][1], BbU + boff1 + ks * 32);
            #pragma unroll
            for (int mt = 0; mt < 2; mt++)
                #pragma unroll
                for (int nt = 0; nt < 4; nt++)
                    mma_f16(acc[mt][nt], af[mt], bf[nt]);
        }
    }

    #pragma unroll
    for (int mt = 0; mt < 2; mt++) {
        int r0 = blockIdx.y * 128 + wm + mt * 16 + (lane >> 2);
        #pragma unroll
        for (int nt = 0; nt < 4; nt++) {
            int c0 = blockIdx.x * 128 + wn + nt * 8 + (lane & 3) * 2;
            if (ro) {
                __half2 h01 = __floats2half2_rn(acc[mt][nt][0], acc[mt][nt][1]);
                __half2 h23 = __floats2half2_rn(acc[mt][nt][2], acc[mt][nt][3]);
                *(__half2*)&H[(size_t)r0 * CC + c0]       = h01;
                *(__half2*)&H[(size_t)(r0 + 8) * CC + c0] = h23;
            } else {
                *(float2*)&C0[(size_t)r0 * CC + c0] =
                    make_float2(acc[mt][nt][0], acc[mt][nt][1]);
                *(float2*)&C0[(size_t)(r0 + 8) * CC + c0] =
                    make_float2(acc[mt][nt][2], acc[mt][nt][3]);
            }
        }
    }
}

// ---------------------------------------------------------------------------
// Kernel A: scores + ALiBi + softmax; writes attn fp32 (d_out) + P fp16 (g_P).
// block=(b,h,16q), 256 thr, 2 CTAs/SM. (R10 configuration — known good.)
// ---------------------------------------------------------------------------
#define QT   16
#define SSST 1028
#define QST 72
#define KST 72
#define KBUFB (128 * KST * 2)    // stage bytes: 18432
__global__ __launch_bounds__(256, 2)
void attn_score_kernel(const __half* __restrict__ Q, const __half* __restrict__ Km,
                       float* __restrict__ attn, __half* __restrict__ Ph)
{
    extern __shared__ char smraw[];
    float*  sS = (float*)smraw;                        // QT*1028 floats
    __half* sQ = (__half*)(smraw + QT * SSST * 4);     // QT*72 halfs
    char*   sK = smraw + QT * SSST * 4 + QT * QST * 2; // 2 * KBUFB
    uint32_t sQu = (uint32_t)__cvta_generic_to_shared(sQ);
    uint32_t sKu = (uint32_t)__cvta_generic_to_shared(sK);

    const int tid  = threadIdx.x;
    const int lane = tid & 31;
    const int warp = tid >> 5;           // 0..7
    const int qb   = blockIdx.x * QT;
    const int h    = blockIdx.y;
    const int b    = blockIdx.z;

    const float scale = 0.125f;
    const float slope = exp2f(-0.5f * (float)(h + 1));

    const int wn = warp;                 // 16-col chunk per warp

    const int lrow = lane & 15;
    const int lkof = (lane & 16) ? 8 : 0;
    const uint32_t koff = ((wn * 16 + lrow) * KST + lkof) * 2;

    const __half* Kb = Km + ((size_t)(b * TT)) * CC + h * DD;

    auto issueK = [&](int c, int buf) {
        const __half* base = Kb + (size_t)(c * 128) * CC;
        #pragma unroll
        for (int i = 0; i < 4; i++) {
            int g = tid + i * 256;              // 1024 granules
            int row = g >> 3, seg = g & 7;
            CPA16(sKu + buf * KBUFB + row * (KST * 2) + seg * 16,
                  base + (size_t)row * CC + seg * 8);
        }
        CPCOMMIT();
    };

    issueK(0, 0);

    // Q tile [16 x 64] halfs -> sQ
    if (tid < 128) {
        const __half* Qb = Q + ((size_t)(b * TT + qb)) * CC + h * DD;
        int r = tid >> 3, seg = tid & 7;
        *(uint4*)(sQ + r * QST + seg * 8) =
            *(const uint4*)(Qb + (size_t)r * CC + seg * 8);
    }
    __syncthreads();

    // preload Q fragments for all 4 k16-steps (loop-invariant; m16 = all QT rows)
    uint32_t aq[4][4];
    {
        uint32_t qoff = sQu + (lrow * QST + lkof) * 2;
        #pragma unroll
        for (int ks = 0; ks < 4; ks++)
            ldsm_x4(aq[ks][0], aq[ks][1], aq[ks][2], aq[ks][3], qoff + ks * 32);
    }

    int buf = 0;
    for (int c = 0; c < 8; c++) {
        if (c + 1 < 8) issueK(c + 1, buf ^ 1);
        if (c < 7) { CPWAIT(1); } else { CPWAIT(0); }
        __syncthreads();

        const uint32_t KU = sKu + buf * KBUFB;
        float cr[2][4];
        #pragma unroll
        for (int nt = 0; nt < 2; nt++)
            #pragma unroll
            for (int i = 0; i < 4; i++) cr[nt][i] = 0.f;

        #pragma unroll
        for (int ks = 0; ks < 4; ks++) {
            uint32_t bf2[2][2];
            ldsm_x4(bf2[0][0], bf2[1][0], bf2[0][1], bf2[1][1], KU + koff + ks * 32);
            mma_f16(cr[0], aq[ks], bf2[0]);
            mma_f16(cr[1], aq[ks], bf2[1]);
        }

        const int kc = c * 128;
        #pragma unroll
        for (int nt = 0; nt < 2; nt++) {
            int r0 = lane >> 2;
            int cl = wn * 16 + nt * 8 + (lane & 3) * 2;
            float q0 = (float)(qb + r0), q8 = q0 + 8.0f;
            float k0f = (float)(kc + cl), k1f = k0f + 1.0f;
            *(float2*)&sS[r0 * SSST + kc + cl] = make_float2(
                cr[nt][0] * scale - slope * fabsf(q0 - k0f),
                cr[nt][1] * scale - slope * fabsf(q0 - k1f));
            *(float2*)&sS[(r0 + 8) * SSST + kc + cl] = make_float2(
                cr[nt][2] * scale - slope * fabsf(q8 - k0f),
                cr[nt][3] * scale - slope * fabsf(q8 - k1f));
        }
        __syncthreads();
        buf ^= 1;
    }

    // softmax: each warp owns 2 rows; write attn fp32 + P fp16
    const size_t attn_base = (((size_t)(b * HH + h)) * TT + qb) * TT;
    #pragma unroll
    for (int rr = 0; rr < 2; rr++) {
        int q = warp * 2 + rr;
        float* row = sS + q * SSST;
        float4 e[8];
        float m = -1e30f;
        #pragma unroll
        for (int it = 0; it < 8; it++) {
            e[it] = *(float4*)(row + it * 128 + lane * 4);
            m = fmaxf(m, fmaxf(fmaxf(e[it].x, e[it].y), fmaxf(e[it].z, e[it].w)));
        }
        #pragma unroll
        for (int off = 16; off; off >>= 1) m = fmaxf(m, __shfl_xor_sync(~0u, m, off));
        float s = 0.f;
        #pragma unroll
        for (int it = 0; it < 8; it++) {
            e[it].x = __expf(e[it].x - m);
            e[it].y = __expf(e[it].y - m);
            e[it].z = __expf(e[it].z - m);
            e[it].w = __expf(e[it].w - m);
            s += (e[it].x + e[it].y) + (e[it].z + e[it].w);
        }
        #pragma unroll
        for (int off = 16; off; off >>= 1) s += __shfl_xor_sync(~0u, s, off);
        float inv = 1.0f / s;
        float*  out  = attn + attn_base + (size_t)q * TT;
        __half* outh = Ph + attn_base + (size_t)q * TT;
        #pragma unroll
        for (int it = 0; it < 8; it++) {
            float4 v = e[it];
            v.x *= inv; v.y *= inv; v.z *= inv; v.w *= inv;
            int cx = it * 128 + lane * 4;
            *(float4*)(out + cx) = v;            // fp32 attn output
            *(uint2*)(outh + cx) = f4_to_h4(v);  // fp16 P for PV
        }
    }
}

// ---------------------------------------------------------------------------
// Kernel B: Y[128x64] = P[128x1024] @ V[1024x64] per (b,h,qtile), all fp16.
// 256 thr, 4-stage cp.async, P via ldmatrix, V via ldmatrix.trans.
// (R10 configuration — known good.)
// ---------------------------------------------------------------------------
#define PST 40
#define VST 72
#define PSTGB (128 * PST * 2)     // 10240
#define VSTGB (32 * VST * 2)      // 4608
__global__ __launch_bounds__(256, 2)
void pv_kernel(const __half* __restrict__ Ph, const __half* __restrict__ V,
               __half* __restrict__ Y)
{
    extern __shared__ char smraw[];
    uint32_t sPu = (uint32_t)__cvta_generic_to_shared(smraw);
    uint32_t sVu = sPu + 4 * PSTGB;

    const int tid  = threadIdx.x;
    const int lane = tid & 31;
    const int warp = tid >> 5;            // 0..7
    const int qb   = blockIdx.x * 128;
    const int h    = blockIdx.y;
    const int b    = blockIdx.z;

    const int wm = (warp >> 1) * 32;
    const int wn = (warp & 1) * 32;

    const int lrow = lane & 15;
    const int lkof = (lane & 16) ? 8 : 0;
    const uint32_t poff0 = ((wm + lrow)      * PST + lkof) * 2;
    const uint32_t poff1 = ((wm + 16 + lrow) * PST + lkof) * 2;
    const uint32_t voff = ((lane & 15) * VST + wn + lkof) * 2;

    const __half* Pb = Ph + (((size_t)(b * HH + h)) * TT + qb) * TT;
    const __half* Vb = V + ((size_t)(b * TT)) * CC + h * DD;

    auto load_stage = [&](int kt, int s) {
        #pragma unroll
        for (int i = 0; i < 2; i++) {
            int g = tid + i * 256;               // 512 P granules
            int row = g >> 2, seg = g & 3;
            CPA16(sPu + s * PSTGB + row * 80 + seg * 16,
                  Pb + (size_t)row * TT + kt * 32 + seg * 8);
        }
        {
            int row = tid >> 3, seg = tid & 7;   // 256 V granules
            CPA16(sVu + s * VSTGB + row * (VST * 2) + seg * 16,
                  Vb + (size_t)(kt * 32 + row) * CC + seg * 8);
        }
        CPCOMMIT();
    };

    load_stage(0, 0);
    load_stage(1, 1);
    load_stage(2, 2);

    float acc[2][4][4];
    #pragma unroll
    for (int i = 0; i < 2; i++)
        #pragma unroll
        for (int j = 0; j < 4; j++)
            #pragma unroll
            for (int k = 0; k < 4; k++) acc[i][j][k] = 0.f;

    const int NT2 = 32;
    for (int kt = 0; kt < NT2; kt++) {
        if (kt <= NT2 - 3)      { CPWAIT(2); }
        else if (kt == NT2 - 2) { CPWAIT(1); }
        else                    { CPWAIT(0); }
        __syncthreads();

        if (kt + 3 < NT2) load_stage(kt + 3, (kt + 3) & 3);

        const uint32_t PtU = sPu + (kt & 3) * PSTGB;
        const uint32_t VtU = sVu + (kt & 3) * VSTGB;

        #pragma unroll
        for (int ks = 0; ks < 2; ks++) {
            uint32_t af[2][4], bf[4][2];
            ldsm_x4(af[0][0], af[0][1], af[0][2], af[0][3], PtU + poff0 + ks * 32);
            ldsm_x4(af[1][0], af[1][1], af[1][2], af[1][3], PtU + poff1 + ks * 32);
            ldsm_x4t(bf[0][0], bf[0][1], bf[1][0], bf[1][1],
                     VtU + voff + ks * 16 * (VST * 2));
            ldsm_x4t(bf[2][0], bf[2][1], bf[3][0], bf[3][1],
                     VtU + voff + 16 * 2 + ks * 16 * (VST * 2));
            #pragma unroll
            for (int mt2 = 0; mt2 < 2; mt2++)
                #pragma unroll
                for (int nt = 0; nt < 4; nt++)
                    mma_f16(acc[mt2][nt], af[mt2], bf[nt]);
        }
    }

    #pragma unroll
    for (int mt2 = 0; mt2 < 2; mt2++) {
        int r0 = qb + wm + mt2 * 16 + (lane >> 2);
        #pragma unroll
        for (int nt = 0; nt < 4; nt++) {
            int c0 = wn + nt * 8 + (lane & 3) * 2;
            __half2 h01 = __floats2half2_rn(acc[mt2][nt][0], acc[mt2][nt][1]);
            __half2 h23 = __floats2half2_rn(acc[mt2][nt][2], acc[mt2][nt][3]);
            *(__half2*)&Y[(size_t)(b * TT + r0) * CC + h * DD + c0]       = h01;
            *(__half2*)&Y[(size_t)(b * TT + r0 + 8) * CC + h * DD + c0]   = h23;
        }
    }
}

// ---------------------------------------------------------------------------
// launch: prepass -> QKV proj -> scores/softmax -> PV -> output proj
// d_out = [ y (B*T*C) fp32 | attn (B*H*T*T) fp32 ]
// ---------------------------------------------------------------------------
extern "C" void kernel_launch(void* const* d_in, const int* in_sizes, int n_in,
                              void* d_out, int out_size)
{
    const float* x  = (const float*)d_in[0];
    const float* Wq = (const float*)d_in[1];
    const float* Wk = (const float*)d_in[2];
    const float* Wv = (const float*)d_in[3];
    const float* Wp = (const float*)d_in[4];

    float* out      = (float*)d_out;
    float* y_out    = out;
    float* attn_out = out + (size_t)BB * TT * CC;

    __half *Qh, *Kh, *Vh, *Yh, *Xh, *Wh, *Pp;
    cudaGetSymbolAddress((void**)&Qh, g_Qh);
    cudaGetSymbolAddress((void**)&Kh, g_Kh);
    cudaGetSymbolAddress((void**)&Vh, g_Vh);
    cudaGetSymbolAddress((void**)&Yh, g_Yh);
    cudaGetSymbolAddress((void**)&Xh, g_Xh);
    cudaGetSymbolAddress((void**)&Wh, g_Wh);
    cudaGetSymbolAddress((void**)&Pp, g_P);

    prepass<<<dim3(1024, 5), 256>>>(x, Wq, Wk, Wv, Wp);

    const size_t gemm_smem = (size_t)8 * GSTG;                        // 147456
    cudaFuncSetAttribute(gemm_f16_nt,
                         cudaFuncAttributeMaxDynamicSharedMemorySize,
                         (int)gemm_smem);

    dim3 gq(CC / 128, BT / 128, 3);
    gemm_f16_nt<<<gq, 512, gemm_smem>>>(Xh, Wh, Qh, Kh, Vh, nullptr, 1);

    const size_t scoreA_smem =
        (size_t)QT * SSST * 4 + QT * QST * 2 + 2 * KBUFB;             // 104960
    cudaFuncSetAttribute(attn_score_kernel,
                         cudaFuncAttributeMaxDynamicSharedMemorySize,
                         (int)scoreA_smem);
    attn_score_kernel<<<dim3(TT / QT, HH, BB), 256, scoreA_smem>>>(
        Qh, Kh, attn_out, Pp);

    const size_t pv_smem = (size_t)4 * (PSTGB + VSTGB);               // 59392
    cudaFuncSetAttribute(pv_kernel,
                         cudaFuncAttributeMaxDynamicSharedMemorySize,
                         (int)pv_smem);
    pv_kernel<<<dim3(TT / 128, HH, BB), 256, pv_smem>>>(Pp, Vh, Yh);

    dim3 gp(CC / 128, BT / 128, 1);
    gemm_f16_nt<<<gp, 512, gemm_smem>>>(Yh, Wh + (size_t)3 * CC * CC,
                                        nullptr, nullptr, nullptr, y_out, 0);
}

// round 14
// speedup vs baseline: 1.3248x; 1.0392x over previous
#include <cuda_runtime.h>
#include <cuda_fp16.h>
#include <math.h>
#include <stdint.h>

#define BB   4
#define TT   1024
#define CC   1024
#define HH   16
#define DD   64
#define BT   (BB*TT)          // 4096

// Scratch (allocation-free rule: __device__ globals)
__device__ __half g_Qh[BT * CC];
__device__ __half g_Kh[BT * CC];
__device__ __half g_Vh[BT * CC];
__device__ __half g_Yh[BT * CC];
__device__ __half g_Xh[BT * CC];          // fp16-rounded x
__device__ __half g_Wh[4 * CC * CC];      // fp16-rounded Wq|Wk|Wv|Wp
__device__ __half g_P[(size_t)BB * HH * TT * TT];   // fp16 attention probs

// Secondary stream + fork/join events, created once at static-init time
// (host-side runtime resources, not device allocations).
struct AuxStream {
    cudaStream_t s1;
    cudaEvent_t  e0, e1;
    AuxStream() {
        cudaStreamCreateWithFlags(&s1, cudaStreamNonBlocking);
        cudaEventCreateWithFlags(&e0, cudaEventDisableTiming);
        cudaEventCreateWithFlags(&e1, cudaEventDisableTiming);
    }
};
static AuxStream g_aux;

// ---------------------------------------------------------------------------
// helpers
// ---------------------------------------------------------------------------
__device__ __forceinline__ uint2 f4_to_h4(float4 v) {
    __half2 a = __floats2half2_rn(v.x, v.y);
    __half2 b = __floats2half2_rn(v.z, v.w);
    uint2 r;
    r.x = *(uint32_t*)&a;
    r.y = *(uint32_t*)&b;
    return r;
}

__device__ __forceinline__ void mma_f16(float* c, const uint32_t* a, const uint32_t* b) {
    asm volatile(
        "mma.sync.aligned.m16n8k16.row.col.f32.f16.f16.f32 "
        "{%0,%1,%2,%3}, {%4,%5,%6,%7}, {%8,%9}, {%0,%1,%2,%3};"
        : "+f"(c[0]), "+f"(c[1]), "+f"(c[2]), "+f"(c[3])
        : "r"(a[0]), "r"(a[1]), "r"(a[2]), "r"(a[3]), "r"(b[0]), "r"(b[1]));
}

__device__ __forceinline__ void ldsm_x4(uint32_t& r0, uint32_t& r1,
                                        uint32_t& r2, uint32_t& r3, uint32_t addr) {
    asm volatile("ldmatrix.sync.aligned.m8n8.x4.shared.b16 {%0,%1,%2,%3}, [%4];"
                 : "=r"(r0), "=r"(r1), "=r"(r2), "=r"(r3) : "r"(addr));
}
__device__ __forceinline__ void ldsm_x4t(uint32_t& r0, uint32_t& r1,
                                         uint32_t& r2, uint32_t& r3, uint32_t addr) {
    asm volatile("ldmatrix.sync.aligned.m8n8.x4.trans.shared.b16 {%0,%1,%2,%3}, [%4];"
                 : "=r"(r0), "=r"(r1), "=r"(r2), "=r"(r3) : "r"(addr));
}

#define CPA16(dst_u32, src_ptr) \
    asm volatile("cp.async.cg.shared.global [%0], [%1], 16;" \
                 :: "r"(dst_u32), "l"(src_ptr))
#define CPCOMMIT() asm volatile("cp.async.commit_group;")
#define CPWAIT(n)  asm volatile("cp.async.wait_group %0;" :: "n"(n))

// ---------------------------------------------------------------------------
// prepass: fp16-round x -> g_Xh, weights -> g_Wh (concat)
// ---------------------------------------------------------------------------
__global__ void prepass(const float* __restrict__ x,
                        const float* __restrict__ wq, const float* __restrict__ wk,
                        const float* __restrict__ wv, const float* __restrict__ wp)
{
    int which = blockIdx.y;
    const float* src;
    __half* dst;
    int n4;
    if (which == 0) { src = x;  dst = g_Xh; n4 = BT * CC / 4; }
    else {
        src = (which == 1) ? wq : (which == 2) ? wk : (which == 3) ? wv : wp;
        dst = g_Wh + (size_t)(which - 1) * CC * CC;
        n4 = CC * CC / 4;
    }
    for (int i = blockIdx.x * blockDim.x + threadIdx.x; i < n4;
         i += gridDim.x * blockDim.x) {
        float4 v = ((const float4*)src)[i];
        ((uint2*)dst)[i] = f4_to_h4(v);
    }
}

// ---------------------------------------------------------------------------
// C[M,N] = A[M,K] @ W[N,K]^T, FP16 MMA m16n8k16, inputs pre-rounded fp16.
// 128x128 tile, BK=32, 512 threads, 4-stage cp.async, ldmatrix fragments.
// (R7/R10 configuration — known good.)
// ---------------------------------------------------------------------------
#define AST 40                   // halfs per row (80 bytes)
#define GSTG (128 * AST * 2)     // stage bytes per array: 10240
#define NTG 32                   // K/32
__global__ __launch_bounds__(512, 1)
void gemm_f16_nt(const __half* __restrict__ A, const __half* __restrict__ Wb,
                 __half* __restrict__ H0, __half* __restrict__ H1,
                 __half* __restrict__ H2, float* __restrict__ C0, int ro)
{
    const __half* Bw = Wb + (size_t)blockIdx.z * CC * CC;
    __half* H = (blockIdx.z == 0) ? H0 : (blockIdx.z == 1 ? H1 : H2);

    extern __shared__ char smraw[];
    uint32_t sAu = (uint32_t)__cvta_generic_to_shared(smraw);
    uint32_t sBu = sAu + 4 * GSTG;

    const int tid  = threadIdx.x;
    const int lane = tid & 31;
    const int warp = tid >> 5;
    const int wm   = (warp & 3) * 32;
    const int wn   = (warp >> 2) * 32;

    const int lrow = lane & 15;
    const int lkof = (lane & 16) ? 8 : 0;     // halfs
    const uint32_t aoff0 = ((wm + lrow)      * AST + lkof) * 2;
    const uint32_t aoff1 = ((wm + 16 + lrow) * AST + lkof) * 2;
    const uint32_t boff0 = ((wn + lrow)      * AST + lkof) * 2;
    const uint32_t boff1 = ((wn + 16 + lrow) * AST + lkof) * 2;

    const __half* Abase = A  + (size_t)(blockIdx.y * 128) * CC;
    const __half* Bbase = Bw + (size_t)(blockIdx.x * 128) * CC;

    auto load_stage = [&](int kt, int s) {
        int row = tid >> 2, seg = tid & 3;               // 512 granules per array
        CPA16(sAu + s * GSTG + row * 80 + seg * 16,
              Abase + (size_t)row * CC + kt * 32 + seg * 8);
        CPA16(sBu + s * GSTG + row * 80 + seg * 16,
              Bbase + (size_t)row * CC + kt * 32 + seg * 8);
        CPCOMMIT();
    };

    load_stage(0, 0);
    load_stage(1, 1);
    load_stage(2, 2);

    float acc[2][4][4];
    #pragma unroll
    for (int i = 0; i < 2; i++)
        #pragma unroll
        for (int j = 0; j < 4; j++)
            #pragma unroll
            for (int k = 0; k < 4; k++) acc[i][j][k] = 0.f;

    for (int kt = 0; kt < NTG; kt++) {
        if (kt <= NTG - 3)      { CPWAIT(2); }
        else if (kt == NTG - 2) { CPWAIT(1); }
        else                    { CPWAIT(0); }
        __syncthreads();

        if (kt + 3 < NTG) load_stage(kt + 3, (kt + 3) & 3);

        const uint32_t AbU = sAu + (kt & 3) * GSTG;
        const uint32_t BbU = sBu + (kt & 3) * GSTG;

        #pragma unroll
        for (int ks = 0; ks < 2; ks++) {                 // 2 x k16
            uint32_t af[2][4], bf[4][2];
            ldsm_x4(af[0][0], af[0][1], af[0][2], af[0][3], AbU + aoff0 + ks * 32);
            ldsm_x4(af[1][0], af[1][1], af[1][2], af[1][3], AbU + aoff1 + ks * 32);
            ldsm_x4(bf[0][0], bf[1][0], bf[0][1], bf[1][1], BbU + boff0 + ks * 32);
            ldsm_x4(bf[2][0], bf[3][0], bf[2][1], bf[3][1], BbU + boff1 + ks * 32);
            #pragma unroll
            for (int mt = 0; mt < 2; mt++)
                #pragma unroll
                for (int nt = 0; nt < 4; nt++)
                    mma_f16(acc[mt][nt], af[mt], bf[nt]);
        }
    }

    #pragma unroll
    for (int mt = 0; mt < 2; mt++) {
        int r0 = blockIdx.y * 128 + wm + mt * 16 + (lane >> 2);
        #pragma unroll
        for (int nt = 0; nt < 4; nt++) {
            int c0 = blockIdx.x * 128 + wn + nt * 8 + (lane & 3) * 2;
            if (ro) {
                __half2 h01 = __floats2half2_rn(acc[mt][nt][0], acc[mt][nt][1]);
                __half2 h23 = __floats2half2_rn(acc[mt][nt][2], acc[mt][nt][3]);
                *(__half2*)&H[(size_t)r0 * CC + c0]       = h01;
                *(__half2*)&H[(size_t)(r0 + 8) * CC + c0] = h23;
            } else {
                *(float2*)&C0[(size_t)r0 * CC + c0] =
                    make_float2(acc[mt][nt][0], acc[mt][nt][1]);
                *(float2*)&C0[(size_t)(r0 + 8) * CC + c0] =
                    make_float2(acc[mt][nt][2], acc[mt][nt][3]);
            }
        }
    }
}

// ---------------------------------------------------------------------------
// Kernel A: scores + ALiBi + softmax; writes attn fp32 (d_out) + P fp16 (g_P).
// block=(b,h,16q), 256 thr, 2 CTAs/SM. (R10 configuration — known good.)
// ---------------------------------------------------------------------------
#define QT   16
#define SSST 1028
#define QST 72
#define KST 72
#define KBUFB (128 * KST * 2)    // stage bytes: 18432
__global__ __launch_bounds__(256, 2)
void attn_score_kernel(const __half* __restrict__ Q, const __half* __restrict__ Km,
                       float* __restrict__ attn, __half* __restrict__ Ph)
{
    extern __shared__ char smraw[];
    float*  sS = (float*)smraw;                        // QT*1028 floats
    __half* sQ = (__half*)(smraw + QT * SSST * 4);     // QT*72 halfs
    char*   sK = smraw + QT * SSST * 4 + QT * QST * 2; // 2 * KBUFB
    uint32_t sQu = (uint32_t)__cvta_generic_to_shared(sQ);
    uint32_t sKu = (uint32_t)__cvta_generic_to_shared(sK);

    const int tid  = threadIdx.x;
    const int lane = tid & 31;
    const int warp = tid >> 5;           // 0..7
    const int qb   = blockIdx.x * QT;
    const int h    = blockIdx.y;
    const int b    = blockIdx.z;

    const float scale = 0.125f;
    const float slope = exp2f(-0.5f * (float)(h + 1));

    const int wn = warp;                 // 16-col chunk per warp

    const int lrow = lane & 15;
    const int lkof = (lane & 16) ? 8 : 0;
    const uint32_t koff = ((wn * 16 + lrow) * KST + lkof) * 2;

    const __half* Kb = Km + ((size_t)(b * TT)) * CC + h * DD;

    auto issueK = [&](int c, int buf) {
        const __half* base = Kb + (size_t)(c * 128) * CC;
        #pragma unroll
        for (int i = 0; i < 4; i++) {
            int g = tid + i * 256;              // 1024 granules
            int row = g >> 3, seg = g & 7;
            CPA16(sKu + buf * KBUFB + row * (KST * 2) + seg * 16,
                  base + (size_t)row * CC + seg * 8);
        }
        CPCOMMIT();
    };

    issueK(0, 0);

    // Q tile [16 x 64] halfs -> sQ
    if (tid < 128) {
        const __half* Qb = Q + ((size_t)(b * TT + qb)) * CC + h * DD;
        int r = tid >> 3, seg = tid & 7;
        *(uint4*)(sQ + r * QST + seg * 8) =
            *(const uint4*)(Qb + (size_t)r * CC + seg * 8);
    }
    __syncthreads();

    // preload Q fragments for all 4 k16-steps (loop-invariant; m16 = all QT rows)
    uint32_t aq[4][4];
    {
        uint32_t qoff = sQu + (lrow * QST + lkof) * 2;
        #pragma unroll
        for (int ks = 0; ks < 4; ks++)
            ldsm_x4(aq[ks][0], aq[ks][1], aq[ks][2], aq[ks][3], qoff + ks * 32);
    }

    int buf = 0;
    for (int c = 0; c < 8; c++) {
        if (c + 1 < 8) issueK(c + 1, buf ^ 1);
        if (c < 7) { CPWAIT(1); } else { CPWAIT(0); }
        __syncthreads();

        const uint32_t KU = sKu + buf * KBUFB;
        float cr[2][4];
        #pragma unroll
        for (int nt = 0; nt < 2; nt++)
            #pragma unroll
            for (int i = 0; i < 4; i++) cr[nt][i] = 0.f;

        #pragma unroll
        for (int ks = 0; ks < 4; ks++) {
            uint32_t bf2[2][2];
            ldsm_x4(bf2[0][0], bf2[1][0], bf2[0][1], bf2[1][1], KU + koff + ks * 32);
            mma_f16(cr[0], aq[ks], bf2[0]);
            mma_f16(cr[1], aq[ks], bf2[1]);
        }

        const int kc = c * 128;
        #pragma unroll
        for (int nt = 0; nt < 2; nt++) {
            int r0 = lane >> 2;
            int cl = wn * 16 + nt * 8 + (lane & 3) * 2;
            float q0 = (float)(qb + r0), q8 = q0 + 8.0f;
            float k0f = (float)(kc + cl), k1f = k0f + 1.0f;
            *(float2*)&sS[r0 * SSST + kc + cl] = make_float2(
                cr[nt][0] * scale - slope * fabsf(q0 - k0f),
                cr[nt][1] * scale - slope * fabsf(q0 - k1f));
            *(float2*)&sS[(r0 + 8) * SSST + kc + cl] = make_float2(
                cr[nt][2] * scale - slope * fabsf(q8 - k0f),
                cr[nt][3] * scale - slope * fabsf(q8 - k1f));
        }
        __syncthreads();
        buf ^= 1;
    }

    // softmax: each warp owns 2 rows; write attn fp32 + P fp16
    const size_t attn_base = (((size_t)(b * HH + h)) * TT + qb) * TT;
    #pragma unroll
    for (int rr = 0; rr < 2; rr++) {
        int q = warp * 2 + rr;
        float* row = sS + q * SSST;
        float4 e[8];
        float m = -1e30f;
        #pragma unroll
        for (int it = 0; it < 8; it++) {
            e[it] = *(float4*)(row + it * 128 + lane * 4);
            m = fmaxf(m, fmaxf(fmaxf(e[it].x, e[it].y), fmaxf(e[it].z, e[it].w)));
        }
        #pragma unroll
        for (int off = 16; off; off >>= 1) m = fmaxf(m, __shfl_xor_sync(~0u, m, off));
        float s = 0.f;
        #pragma unroll
        for (int it = 0; it < 8; it++) {
            e[it].x = __expf(e[it].x - m);
            e[it].y = __expf(e[it].y - m);
            e[it].z = __expf(e[it].z - m);
            e[it].w = __expf(e[it].w - m);
            s += (e[it].x + e[it].y) + (e[it].z + e[it].w);
        }
        #pragma unroll
        for (int off = 16; off; off >>= 1) s += __shfl_xor_sync(~0u, s, off);
        float inv = 1.0f / s;
        float*  out  = attn + attn_base + (size_t)q * TT;
        __half* outh = Ph + attn_base + (size_t)q * TT;
        #pragma unroll
        for (int it = 0; it < 8; it++) {
            float4 v = e[it];
            v.x *= inv; v.y *= inv; v.z *= inv; v.w *= inv;
            int cx = it * 128 + lane * 4;
            *(float4*)(out + cx) = v;            // fp32 attn output
            *(uint2*)(outh + cx) = f4_to_h4(v);  // fp16 P for PV
        }
    }
}

// ---------------------------------------------------------------------------
// Kernel B: Y[128x64] = P[128x1024] @ V[1024x64] per (b,h,qtile), all fp16.
// 256 thr, 4-stage cp.async, P via ldmatrix, V via ldmatrix.trans.
// (R10 configuration — known good.)
// ---------------------------------------------------------------------------
#define PST 40
#define VST 72
#define PSTGB (128 * PST * 2)     // 10240
#define VSTGB (32 * VST * 2)      // 4608
__global__ __launch_bounds__(256, 2)
void pv_kernel(const __half* __restrict__ Ph, const __half* __restrict__ V,
               __half* __restrict__ Y)
{
    extern __shared__ char smraw[];
    uint32_t sPu = (uint32_t)__cvta_generic_to_shared(smraw);
    uint32_t sVu = sPu + 4 * PSTGB;

    const int tid  = threadIdx.x;
    const int lane = tid & 31;
    const int warp = tid >> 5;            // 0..7
    const int qb   = blockIdx.x * 128;
    const int h    = blockIdx.y;
    const int b    = blockIdx.z;

    const int wm = (warp >> 1) * 32;
    const int wn = (warp & 1) * 32;

    const int lrow = lane & 15;
    const int lkof = (lane & 16) ? 8 : 0;
    const uint32_t poff0 = ((wm + lrow)      * PST + lkof) * 2;
    const uint32_t poff1 = ((wm + 16 + lrow) * PST + lkof) * 2;
    const uint32_t voff = ((lane & 15) * VST + wn + lkof) * 2;

    const __half* Pb = Ph + (((size_t)(b * HH + h)) * TT + qb) * TT;
    const __half* Vb = V + ((size_t)(b * TT)) * CC + h * DD;

    auto load_stage = [&](int kt, int s) {
        #pragma unroll
        for (int i = 0; i < 2; i++) {
            int g = tid + i * 256;               // 512 P granules
            int row = g >> 2, seg = g & 3;
            CPA16(sPu + s * PSTGB + row * 80 + seg * 16,
                  Pb + (size_t)row * TT + kt * 32 + seg * 8);
        }
        {
            int row = tid >> 3, seg = tid & 7;   // 256 V granules
            CPA16(sVu + s * VSTGB + row * (VST * 2) + seg * 16,
                  Vb + (size_t)(kt * 32 + row) * CC + seg * 8);
        }
        CPCOMMIT();
    };

    load_stage(0, 0);
    load_stage(1, 1);
    load_stage(2, 2);

    float acc[2][4][4];
    #pragma unroll
    for (int i = 0; i < 2; i++)
        #pragma unroll
        for (int j = 0; j < 4; j++)
            #pragma unroll
            for (int k = 0; k < 4; k++) acc[i][j][k] = 0.f;

    const int NT2 = 32;
    for (int kt = 0; kt < NT2; kt++) {
        if (kt <= NT2 - 3)      { CPWAIT(2); }
        else if (kt == NT2 - 2) { CPWAIT(1); }
        else                    { CPWAIT(0); }
        __syncthreads();

        if (kt + 3 < NT2) load_stage(kt + 3, (kt + 3) & 3);

        const uint32_t PtU = sPu + (kt & 3) * PSTGB;
        const uint32_t VtU = sVu + (kt & 3) * VSTGB;

        #pragma unroll
        for (int ks = 0; ks < 2; ks++) {
            uint32_t af[2][4], bf[4][2];
            ldsm_x4(af[0][0], af[0][1], af[0][2], af[0][3], PtU + poff0 + ks * 32);
            ldsm_x4(af[1][0], af[1][1], af[1][2], af[1][3], PtU + poff1 + ks * 32);
            ldsm_x4t(bf[0][0], bf[0][1], bf[1][0], bf[1][1],
                     VtU + voff + ks * 16 * (VST * 2));
            ldsm_x4t(bf[2][0], bf[2][1], bf[3][0], bf[3][1],
                     VtU + voff + 16 * 2 + ks * 16 * (VST * 2));
            #pragma unroll
            for (int mt2 = 0; mt2 < 2; mt2++)
                #pragma unroll
                for (int nt = 0; nt < 4; nt++)
                    mma_f16(acc[mt2][nt], af[mt2], bf[nt]);
        }
    }

    #pragma unroll
    for (int mt2 = 0; mt2 < 2; mt2++) {
        int r0 = qb + wm + mt2 * 16 + (lane >> 2);
        #pragma unroll
        for (int nt = 0; nt < 4; nt++) {
            int c0 = wn + nt * 8 + (lane & 3) * 2;
            __half2 h01 = __floats2half2_rn(acc[mt2][nt][0], acc[mt2][nt][1]);
            __half2 h23 = __floats2half2_rn(acc[mt2][nt][2], acc[mt2][nt][3]);
            *(__half2*)&Y[(size_t)(b * TT + r0) * CC + h * DD + c0]       = h01;
            *(__half2*)&Y[(size_t)(b * TT + r0 + 8) * CC + h * DD + c0]   = h23;
        }
    }
}

// ---------------------------------------------------------------------------
// launch: prepass -> [QK proj | V proj (stream s1)] -> scores/softmax ->
//         join -> PV -> output proj
// d_out = [ y (B*T*C) fp32 | attn (B*H*T*T) fp32 ]
// ---------------------------------------------------------------------------
extern "C" void kernel_launch(void* const* d_in, const int* in_sizes, int n_in,
                              void* d_out, int out_size)
{
    const float* x  = (const float*)d_in[0];
    const float* Wq = (const float*)d_in[1];
    const float* Wk = (const float*)d_in[2];
    const float* Wv = (const float*)d_in[3];
    const float* Wp = (const float*)d_in[4];

    float* out      = (float*)d_out;
    float* y_out    = out;
    float* attn_out = out + (size_t)BB * TT * CC;

    __half *Qh, *Kh, *Vh, *Yh, *Xh, *Wh, *Pp;
    cudaGetSymbolAddress((void**)&Qh, g_Qh);
    cudaGetSymbolAddress((void**)&Kh, g_Kh);
    cudaGetSymbolAddress((void**)&Vh, g_Vh);
    cudaGetSymbolAddress((void**)&Yh, g_Yh);
    cudaGetSymbolAddress((void**)&Xh, g_Xh);
    cudaGetSymbolAddress((void**)&Wh, g_Wh);
    cudaGetSymbolAddress((void**)&Pp, g_P);

    const size_t gemm_smem = (size_t)8 * GSTG;                        // 81920
    cudaFuncSetAttribute(gemm_f16_nt,
                         cudaFuncAttributeMaxDynamicSharedMemorySize,
                         (int)gemm_smem);
    const size_t scoreA_smem =
        (size_t)QT * SSST * 4 + QT * QST * 2 + 2 * KBUFB;             // 104960
    cudaFuncSetAttribute(attn_score_kernel,
                         cudaFuncAttributeMaxDynamicSharedMemorySize,
                         (int)scoreA_smem);
    const size_t pv_smem = (size_t)4 * (PSTGB + VSTGB);               // 59392
    cudaFuncSetAttribute(pv_kernel,
                         cudaFuncAttributeMaxDynamicSharedMemorySize,
                         (int)pv_smem);

    prepass<<<dim3(1024, 5), 256>>>(x, Wq, Wk, Wv, Wp);

    // fork: V projection runs on s1, overlapping QK proj + score
    cudaEventRecord(g_aux.e0, 0);
    cudaStreamWaitEvent(g_aux.s1, g_aux.e0, 0);
    dim3 gv(CC / 128, BT / 128, 1);
    gemm_f16_nt<<<gv, 512, gemm_smem, g_aux.s1>>>(
        Xh, Wh + (size_t)2 * CC * CC, Vh, Vh, Vh, nullptr, 1);
    cudaEventRecord(g_aux.e1, g_aux.s1);

    // Q and K projections (z=0 -> Q, z=1 -> K)
    dim3 gqk(CC / 128, BT / 128, 2);
    gemm_f16_nt<<<gqk, 512, gemm_smem>>>(Xh, Wh, Qh, Kh, Kh, nullptr, 1);

    attn_score_kernel<<<dim3(TT / QT, HH, BB), 256, scoreA_smem>>>(
        Qh, Kh, attn_out, Pp);

    // join: pv needs V from s1
    cudaStreamWaitEvent(0, g_aux.e1, 0);
    pv_kernel<<<dim3(TT / 128, HH, BB), 256, pv_smem>>>(Pp, Vh, Yh);

    dim3 gp(CC / 128, BT / 128, 1);
    gemm_f16_nt<<<gp, 512, gemm_smem>>>(Yh, Wh + (size_t)3 * CC * CC,
                                        nullptr, nullptr, nullptr, y_out, 0);
}

// round 15
// speedup vs baseline: 1.3295x; 1.0035x over previous
#include <cuda_runtime.h>
#include <cuda_fp16.h>
#include <math.h>
#include <stdint.h>

#define BB   4
#define TT   1024
#define CC   1024
#define HH   16
#define DD   64
#define BT   (BB*TT)          // 4096

// Scratch (allocation-free rule: __device__ globals)
__device__ __half g_Qh[BT * CC];
__device__ __half g_Kh[BT * CC];
__device__ __half g_Vh[BT * CC];
__device__ __half g_Yh[BT * CC];
__device__ __half g_Xh[BT * CC];          // fp16-rounded x
__device__ __half g_Wh[4 * CC * CC];      // fp16-rounded Wq|Wk|Wv|Wp
__device__ __half g_P[(size_t)BB * HH * TT * TT];   // fp16 attention probs

// ---------------------------------------------------------------------------
// helpers
// ---------------------------------------------------------------------------
__device__ __forceinline__ uint2 f4_to_h4(float4 v) {
    __half2 a = __floats2half2_rn(v.x, v.y);
    __half2 b = __floats2half2_rn(v.z, v.w);
    uint2 r;
    r.x = *(uint32_t*)&a;
    r.y = *(uint32_t*)&b;
    return r;
}

__device__ __forceinline__ void mma_f16(float* c, const uint32_t* a, const uint32_t* b) {
    asm volatile(
        "mma.sync.aligned.m16n8k16.row.col.f32.f16.f16.f32 "
        "{%0,%1,%2,%3}, {%4,%5,%6,%7}, {%8,%9}, {%0,%1,%2,%3};"
        : "+f"(c[0]), "+f"(c[1]), "+f"(c[2]), "+f"(c[3])
        : "r"(a[0]), "r"(a[1]), "r"(a[2]), "r"(a[3]), "r"(b[0]), "r"(b[1]));
}

__device__ __forceinline__ void ldsm_x4(uint32_t& r0, uint32_t& r1,
                                        uint32_t& r2, uint32_t& r3, uint32_t addr) {
    asm volatile("ldmatrix.sync.aligned.m8n8.x4.shared.b16 {%0,%1,%2,%3}, [%4];"
                 : "=r"(r0), "=r"(r1), "=r"(r2), "=r"(r3) : "r"(addr));
}
__device__ __forceinline__ void ldsm_x4t(uint32_t& r0, uint32_t& r1,
                                         uint32_t& r2, uint32_t& r3, uint32_t addr) {
    asm volatile("ldmatrix.sync.aligned.m8n8.x4.trans.shared.b16 {%0,%1,%2,%3}, [%4];"
                 : "=r"(r0), "=r"(r1), "=r"(r2), "=r"(r3) : "r"(addr));
}

// streaming stores (write-through, no L2 allocate) for never-re-read outputs
__device__ __forceinline__ void stwt_f4(float* p, float4 v) {
    asm volatile("st.global.wt.v4.f32 [%0], {%1,%2,%3,%4};"
                 :: "l"(p), "f"(v.x), "f"(v.y), "f"(v.z), "f"(v.w) : "memory");
}
__device__ __forceinline__ void stwt_u2(__half* p, uint2 v) {
    asm volatile("st.global.wt.v2.u32 [%0], {%1,%2};"
                 :: "l"(p), "r"(v.x), "r"(v.y) : "memory");
}
__device__ __forceinline__ void stwt_f2(float* p, float2 v) {
    asm volatile("st.global.wt.v2.f32 [%0], {%1,%2};"
                 :: "l"(p), "f"(v.x), "f"(v.y) : "memory");
}

#define CPA16(dst_u32, src_ptr) \
    asm volatile("cp.async.cg.shared.global [%0], [%1], 16;" \
                 :: "r"(dst_u32), "l"(src_ptr))
#define CPCOMMIT() asm volatile("cp.async.commit_group;")
#define CPWAIT(n)  asm volatile("cp.async.wait_group %0;" :: "n"(n))

// ---------------------------------------------------------------------------
// prepass: fp16-round x -> g_Xh, weights -> g_Wh (concat)
// ---------------------------------------------------------------------------
__global__ void prepass(const float* __restrict__ x,
                        const float* __restrict__ wq, const float* __restrict__ wk,
                        const float* __restrict__ wv, const float* __restrict__ wp)
{
    int which = blockIdx.y;
    const float* src;
    __half* dst;
    int n4;
    if (which == 0) { src = x;  dst = g_Xh; n4 = BT * CC / 4; }
    else {
        src = (which == 1) ? wq : (which == 2) ? wk : (which == 3) ? wv : wp;
        dst = g_Wh + (size_t)(which - 1) * CC * CC;
        n4 = CC * CC / 4;
    }
    for (int i = blockIdx.x * blockDim.x + threadIdx.x; i < n4;
         i += gridDim.x * blockDim.x) {
        float4 v = ((const float4*)src)[i];
        ((uint2*)dst)[i] = f4_to_h4(v);
    }
}

// ---------------------------------------------------------------------------
// C[M,N] = A[M,K] @ W[N,K]^T, FP16 MMA m16n8k16, inputs pre-rounded fp16.
// 128x128 tile, BK=32, 512 threads, 4-stage cp.async, ldmatrix fragments.
// (R7/R10 configuration — known good.)
// ---------------------------------------------------------------------------
#define AST 40                   // halfs per row (80 bytes)
#define GSTG (128 * AST * 2)     // stage bytes per array: 10240
#define NTG 32                   // K/32
__global__ __launch_bounds__(512, 1)
void gemm_f16_nt(const __half* __restrict__ A, const __half* __restrict__ Wb,
                 __half* __restrict__ H0, __half* __restrict__ H1,
                 __half* __restrict__ H2, float* __restrict__ C0, int ro)
{
    const __half* Bw = Wb + (size_t)blockIdx.z * CC * CC;
    __half* H = (blockIdx.z == 0) ? H0 : (blockIdx.z == 1 ? H1 : H2);

    extern __shared__ char smraw[];
    uint32_t sAu = (uint32_t)__cvta_generic_to_shared(smraw);
    uint32_t sBu = sAu + 4 * GSTG;

    const int tid  = threadIdx.x;
    const int lane = tid & 31;
    const int warp = tid >> 5;
    const int wm   = (warp & 3) * 32;
    const int wn   = (warp >> 2) * 32;

    const int lrow = lane & 15;
    const int lkof = (lane & 16) ? 8 : 0;     // halfs
    const uint32_t aoff0 = ((wm + lrow)      * AST + lkof) * 2;
    const uint32_t aoff1 = ((wm + 16 + lrow) * AST + lkof) * 2;
    const uint32_t boff0 = ((wn + lrow)      * AST + lkof) * 2;
    const uint32_t boff1 = ((wn + 16 + lrow) * AST + lkof) * 2;

    const __half* Abase = A  + (size_t)(blockIdx.y * 128) * CC;
    const __half* Bbase = Bw + (size_t)(blockIdx.x * 128) * CC;

    auto load_stage = [&](int kt, int s) {
        int row = tid >> 2, seg = tid & 3;               // 512 granules per array
        CPA16(sAu + s * GSTG + row * 80 + seg * 16,
              Abase + (size_t)row * CC + kt * 32 + seg * 8);
        CPA16(sBu + s * GSTG + row * 80 + seg * 16,
              Bbase + (size_t)row * CC + kt * 32 + seg * 8);
        CPCOMMIT();
    };

    load_stage(0, 0);
    load_stage(1, 1);
    load_stage(2, 2);

    float acc[2][4][4];
    #pragma unroll
    for (int i = 0; i < 2; i++)
        #pragma unroll
        for (int j = 0; j < 4; j++)
            #pragma unroll
            for (int k = 0; k < 4; k++) acc[i][j][k] = 0.f;

    for (int kt = 0; kt < NTG; kt++) {
        if (kt <= NTG - 3)      { CPWAIT(2); }
        else if (kt == NTG - 2) { CPWAIT(1); }
        else                    { CPWAIT(0); }
        __syncthreads();

        if (kt + 3 < NTG) load_stage(kt + 3, (kt + 3) & 3);

        const uint32_t AbU = sAu + (kt & 3) * GSTG;
        const uint32_t BbU = sBu + (kt & 3) * GSTG;

        #pragma unroll
        for (int ks = 0; ks < 2; ks++) {                 // 2 x k16
            uint32_t af[2][4], bf[4][2];
            ldsm_x4(af[0][0], af[0][1], af[0][2], af[0][3], AbU + aoff0 + ks * 32);
            ldsm_x4(af[1][0], af[1][1], af[1][2], af[1][3], AbU + aoff1 + ks * 32);
            ldsm_x4(bf[0][0], bf[1][0], bf[0][1], bf[1][1], BbU + boff0 + ks * 32);
            ldsm_x4(bf[2][0], bf[3][0], bf[2][1], bf[3][1], BbU + boff1 + ks * 32);
            #pragma unroll
            for (int mt = 0; mt < 2; mt++)
                #pragma unroll
                for (int nt = 0; nt < 4; nt++)
                    mma_f16(acc[mt][nt], af[mt], bf[nt]);
        }
    }

    #pragma unroll
    for (int mt = 0; mt < 2; mt++) {
        int r0 = blockIdx.y * 128 + wm + mt * 16 + (lane >> 2);
        #pragma unroll
        for (int nt = 0; nt < 4; nt++) {
            int c0 = blockIdx.x * 128 + wn + nt * 8 + (lane & 3) * 2;
            if (ro) {
                __half2 h01 = __floats2half2_rn(acc[mt][nt][0], acc[mt][nt][1]);
                __half2 h23 = __floats2half2_rn(acc[mt][nt][2], acc[mt][nt][3]);
                *(__half2*)&H[(size_t)r0 * CC + c0]       = h01;
                *(__half2*)&H[(size_t)(r0 + 8) * CC + c0] = h23;
            } else {
                // final y output: never re-read -> streaming store
                stwt_f2(&C0[(size_t)r0 * CC + c0],
                        make_float2(acc[mt][nt][0], acc[mt][nt][1]));
                stwt_f2(&C0[(size_t)(r0 + 8) * CC + c0],
                        make_float2(acc[mt][nt][2], acc[mt][nt][3]));
            }
        }
    }
}

// ---------------------------------------------------------------------------
// Kernel A: scores + ALiBi + softmax; writes attn fp32 (d_out) + P fp16 (g_P)
// via streaming stores (keeps K tiles L2-resident).
// block=(b,h,16q), 256 thr, 2 CTAs/SM. (R10 configuration.)
// ---------------------------------------------------------------------------
#define QT   16
#define SSST 1028
#define QST 72
#define KST 72
#define KBUFB (128 * KST * 2)    // stage bytes: 18432
__global__ __launch_bounds__(256, 2)
void attn_score_kernel(const __half* __restrict__ Q, const __half* __restrict__ Km,
                       float* __restrict__ attn, __half* __restrict__ Ph)
{
    extern __shared__ char smraw[];
    float*  sS = (float*)smraw;                        // QT*1028 floats
    __half* sQ = (__half*)(smraw + QT * SSST * 4);     // QT*72 halfs
    char*   sK = smraw + QT * SSST * 4 + QT * QST * 2; // 2 * KBUFB
    uint32_t sQu = (uint32_t)__cvta_generic_to_shared(sQ);
    uint32_t sKu = (uint32_t)__cvta_generic_to_shared(sK);

    const int tid  = threadIdx.x;
    const int lane = tid & 31;
    const int warp = tid >> 5;           // 0..7
    const int qb   = blockIdx.x * QT;
    const int h    = blockIdx.y;
    const int b    = blockIdx.z;

    const float scale = 0.125f;
    const float slope = exp2f(-0.5f * (float)(h + 1));

    const int wn = warp;                 // 16-col chunk per warp

    const int lrow = lane & 15;
    const int lkof = (lane & 16) ? 8 : 0;
    const uint32_t koff = ((wn * 16 + lrow) * KST + lkof) * 2;

    const __half* Kb = Km + ((size_t)(b * TT)) * CC + h * DD;

    auto issueK = [&](int c, int buf) {
        const __half* base = Kb + (size_t)(c * 128) * CC;
        #pragma unroll
        for (int i = 0; i < 4; i++) {
            int g = tid + i * 256;              // 1024 granules
            int row = g >> 3, seg = g & 7;
            CPA16(sKu + buf * KBUFB + row * (KST * 2) + seg * 16,
                  base + (size_t)row * CC + seg * 8);
        }
        CPCOMMIT();
    };

    issueK(0, 0);

    // Q tile [16 x 64] halfs -> sQ
    if (tid < 128) {
        const __half* Qb = Q + ((size_t)(b * TT + qb)) * CC + h * DD;
        int r = tid >> 3, seg = tid & 7;
        *(uint4*)(sQ + r * QST + seg * 8) =
            *(const uint4*)(Qb + (size_t)r * CC + seg * 8);
    }
    __syncthreads();

    // preload Q fragments for all 4 k16-steps (loop-invariant; m16 = all QT rows)
    uint32_t aq[4][4];
    {
        uint32_t qoff = sQu + (lrow * QST + lkof) * 2;
        #pragma unroll
        for (int ks = 0; ks < 4; ks++)
            ldsm_x4(aq[ks][0], aq[ks][1], aq[ks][2], aq[ks][3], qoff + ks * 32);
    }

    int buf = 0;
    for (int c = 0; c < 8; c++) {
        if (c + 1 < 8) issueK(c + 1, buf ^ 1);
        if (c < 7) { CPWAIT(1); } else { CPWAIT(0); }
        __syncthreads();

        const uint32_t KU = sKu + buf * KBUFB;
        float cr[2][4];
        #pragma unroll
        for (int nt = 0; nt < 2; nt++)
            #pragma unroll
            for (int i = 0; i < 4; i++) cr[nt][i] = 0.f;

        #pragma unroll
        for (int ks = 0; ks < 4; ks++) {
            uint32_t bf2[2][2];
            ldsm_x4(bf2[0][0], bf2[1][0], bf2[0][1], bf2[1][1], KU + koff + ks * 32);
            mma_f16(cr[0], aq[ks], bf2[0]);
            mma_f16(cr[1], aq[ks], bf2[1]);
        }

        const int kc = c * 128;
        #pragma unroll
        for (int nt = 0; nt < 2; nt++) {
            int r0 = lane >> 2;
            int cl = wn * 16 + nt * 8 + (lane & 3) * 2;
            float q0 = (float)(qb + r0), q8 = q0 + 8.0f;
            float k0f = (float)(kc + cl), k1f = k0f + 1.0f;
            *(float2*)&sS[r0 * SSST + kc + cl] = make_float2(
                cr[nt][0] * scale - slope * fabsf(q0 - k0f),
                cr[nt][1] * scale - slope * fabsf(q0 - k1f));
            *(float2*)&sS[(r0 + 8) * SSST + kc + cl] = make_float2(
                cr[nt][2] * scale - slope * fabsf(q8 - k0f),
                cr[nt][3] * scale - slope * fabsf(q8 - k1f));
        }
        __syncthreads();
        buf ^= 1;
    }

    // softmax: each warp owns 2 rows; streaming-write attn fp32 + P fp16
    const size_t attn_base = (((size_t)(b * HH + h)) * TT + qb) * TT;
    #pragma unroll
    for (int rr = 0; rr < 2; rr++) {
        int q = warp * 2 + rr;
        float* row = sS + q * SSST;
        float4 e[8];
        float m = -1e30f;
        #pragma unroll
        for (int it = 0; it < 8; it++) {
            e[it] = *(float4*)(row + it * 128 + lane * 4);
            m = fmaxf(m, fmaxf(fmaxf(e[it].x, e[it].y), fmaxf(e[it].z, e[it].w)));
        }
        #pragma unroll
        for (int off = 16; off; off >>= 1) m = fmaxf(m, __shfl_xor_sync(~0u, m, off));
        float s = 0.f;
        #pragma unroll
        for (int it = 0; it < 8; it++) {
            e[it].x = __expf(e[it].x - m);
            e[it].y = __expf(e[it].y - m);
            e[it].z = __expf(e[it].z - m);
            e[it].w = __expf(e[it].w - m);
            s += (e[it].x + e[it].y) + (e[it].z + e[it].w);
        }
        #pragma unroll
        for (int off = 16; off; off >>= 1) s += __shfl_xor_sync(~0u, s, off);
        float inv = 1.0f / s;
        float*  out  = attn + attn_base + (size_t)q * TT;
        __half* outh = Ph + attn_base + (size_t)q * TT;
        #pragma unroll
        for (int it = 0; it < 8; it++) {
            float4 v = e[it];
            v.x *= inv; v.y *= inv; v.z *= inv; v.w *= inv;
            int cx = it * 128 + lane * 4;
            stwt_f4(out + cx, v);              // fp32 attn (streaming)
            stwt_u2(outh + cx, f4_to_h4(v));   // fp16 P (streaming)
        }
    }
}

// ---------------------------------------------------------------------------
// Kernel B: Y[128x64] = P[128x1024] @ V[1024x64] per (b,h,qtile), all fp16.
// 256 thr, 4-stage cp.async, P via ldmatrix, V via ldmatrix.trans.
// (R10 configuration — known good.)
// ---------------------------------------------------------------------------
#define PST 40
#define VST 72
#define PSTGB (128 * PST * 2)     // 10240
#define VSTGB (32 * VST * 2)      // 4608
__global__ __launch_bounds__(256, 2)
void pv_kernel(const __half* __restrict__ Ph, const __half* __restrict__ V,
               __half* __restrict__ Y)
{
    extern __shared__ char smraw[];
    uint32_t sPu = (uint32_t)__cvta_generic_to_shared(smraw);
    uint32_t sVu = sPu + 4 * PSTGB;

    const int tid  = threadIdx.x;
    const int lane = tid & 31;
    const int warp = tid >> 5;            // 0..7
    const int qb   = blockIdx.x * 128;
    const int h    = blockIdx.y;
    const int b    = blockIdx.z;

    const int wm = (warp >> 1) * 32;
    const int wn = (warp & 1) * 32;

    const int lrow = lane & 15;
    const int lkof = (lane & 16) ? 8 : 0;
    const uint32_t poff0 = ((wm + lrow)      * PST + lkof) * 2;
    const uint32_t poff1 = ((wm + 16 + lrow) * PST + lkof) * 2;
    const uint32_t voff = ((lane & 15) * VST + wn + lkof) * 2;

    const __half* Pb = Ph + (((size_t)(b * HH + h)) * TT + qb) * TT;
    const __half* Vb = V + ((size_t)(b * TT)) * CC + h * DD;

    auto load_stage = [&](int kt, int s) {
        #pragma unroll
        for (int i = 0; i < 2; i++) {
            int g = tid + i * 256;               // 512 P granules
            int row = g >> 2, seg = g & 3;
            CPA16(sPu + s * PSTGB + row * 80 + seg * 16,
                  Pb + (size_t)row * TT + kt * 32 + seg * 8);
        }
        {
            int row = tid >> 3, seg = tid & 7;   // 256 V granules
            CPA16(sVu + s * VSTGB + row * (VST * 2) + seg * 16,
                  Vb + (size_t)(kt * 32 + row) * CC + seg * 8);
        }
        CPCOMMIT();
    };

    load_stage(0, 0);
    load_stage(1, 1);
    load_stage(2, 2);

    float acc[2][4][4];
    #pragma unroll
    for (int i = 0; i < 2; i++)
        #pragma unroll
        for (int j = 0; j < 4; j++)
            #pragma unroll
            for (int k = 0; k < 4; k++) acc[i][j][k] = 0.f;

    const int NT2 = 32;
    for (int kt = 0; kt < NT2; kt++) {
        if (kt <= NT2 - 3)      { CPWAIT(2); }
        else if (kt == NT2 - 2) { CPWAIT(1); }
        else                    { CPWAIT(0); }
        __syncthreads();

        if (kt + 3 < NT2) load_stage(kt + 3, (kt + 3) & 3);

        const uint32_t PtU = sPu + (kt & 3) * PSTGB;
        const uint32_t VtU = sVu + (kt & 3) * VSTGB;

        #pragma unroll
        for (int ks = 0; ks < 2; ks++) {
            uint32_t af[2][4], bf[4][2];
            ldsm_x4(af[0][0], af[0][1], af[0][2], af[0][3], PtU + poff0 + ks * 32);
            ldsm_x4(af[1][0], af[1][1], af[1][2], af[1][3], PtU + poff1 + ks * 32);
            ldsm_x4t(bf[0][0], bf[0][1], bf[1][0], bf[1][1],
                     VtU + voff + ks * 16 * (VST * 2));
            ldsm_x4t(bf[2][0], bf[2][1], bf[3][0], bf[3][1],
                     VtU + voff + 16 * 2 + ks * 16 * (VST * 2));
            #pragma unroll
            for (int mt2 = 0; mt2 < 2; mt2++)
                #pragma unroll
                for (int nt = 0; nt < 4; nt++)
                    mma_f16(acc[mt2][nt], af[mt2], bf[nt]);
        }
    }

    #pragma unroll
    for (int mt2 = 0; mt2 < 2; mt2++) {
        int r0 = qb + wm + mt2 * 16 + (lane >> 2);
        #pragma unroll
        for (int nt = 0; nt < 4; nt++) {
            int c0 = wn + nt * 8 + (lane & 3) * 2;
            __half2 h01 = __floats2half2_rn(acc[mt2][nt][0], acc[mt2][nt][1]);
            __half2 h23 = __floats2half2_rn(acc[mt2][nt][2], acc[mt2][nt][3]);
            *(__half2*)&Y[(size_t)(b * TT + r0) * CC + h * DD + c0]       = h01;
            *(__half2*)&Y[(size_t)(b * TT + r0 + 8) * CC + h * DD + c0]   = h23;
        }
    }
}

// ---------------------------------------------------------------------------
// launch: prepass -> QKV proj -> scores/softmax -> PV -> output proj
// d_out = [ y (B*T*C) fp32 | attn (B*H*T*T) fp32 ]
// ---------------------------------------------------------------------------
extern "C" void kernel_launch(void* const* d_in, const int* in_sizes, int n_in,
                              void* d_out, int out_size)
{
    const float* x  = (const float*)d_in[0];
    const float* Wq = (const float*)d_in[1];
    const float* Wk = (const float*)d_in[2];
    const float* Wv = (const float*)d_in[3];
    const float* Wp = (const float*)d_in[4];

    float* out      = (float*)d_out;
    float* y_out    = out;
    float* attn_out = out + (size_t)BB * TT * CC;

    __half *Qh, *Kh, *Vh, *Yh, *Xh, *Wh, *Pp;
    cudaGetSymbolAddress((void**)&Qh, g_Qh);
    cudaGetSymbolAddress((void**)&Kh, g_Kh);
    cudaGetSymbolAddress((void**)&Vh, g_Vh);
    cudaGetSymbolAddress((void**)&Yh, g_Yh);
    cudaGetSymbolAddress((void**)&Xh, g_Xh);
    cudaGetSymbolAddress((void**)&Wh, g_Wh);
    cudaGetSymbolAddress((void**)&Pp, g_P);

    prepass<<<dim3(1024, 5), 256>>>(x, Wq, Wk, Wv, Wp);

    const size_t gemm_smem = (size_t)8 * GSTG;                        // 81920
    cudaFuncSetAttribute(gemm_f16_nt,
                         cudaFuncAttributeMaxDynamicSharedMemorySize,
                         (int)gemm_smem);

    dim3 gq(CC / 128, BT / 128, 3);
    gemm_f16_nt<<<gq, 512, gemm_smem>>>(Xh, Wh, Qh, Kh, Vh, nullptr, 1);

    const size_t scoreA_smem =
        (size_t)QT * SSST * 4 + QT * QST * 2 + 2 * KBUFB;             // 104960
    cudaFuncSetAttribute(attn_score_kernel,
                         cudaFuncAttributeMaxDynamicSharedMemorySize,
                         (int)scoreA_smem);
    attn_score_kernel<<<dim3(TT / QT, HH, BB), 256, scoreA_smem>>>(
        Qh, Kh, attn_out, Pp);

    const size_t pv_smem = (size_t)4 * (PSTGB + VSTGB);               // 59392
    cudaFuncSetAttribute(pv_kernel,
                         cudaFuncAttributeMaxDynamicSharedMemorySize,
                         (int)pv_smem);
    pv_kernel<<<dim3(TT / 128, HH, BB), 256, pv_smem>>>(Pp, Vh, Yh);

    dim3 gp(CC / 128, BT / 128, 1);
    gemm_f16_nt<<<gp, 512, gemm_smem>>>(Yh, Wh + (size_t)3 * CC * CC,
                                        nullptr, nullptr, nullptr, y_out, 0);
}